// round 7
// baseline (speedup 1.0000x reference)
#include <cuda_runtime.h>
#include <cuda_fp16.h>
#include <stdint.h>
#include <stddef.h>
#include <math.h>

#define NB   4
#define NP   1024
#define DD   256
#define HWT  4096
#define HEADS 8
#define DH   32

#define LF_ELEMS  ((size_t)NB*NP*DD)
#define GF_ELEMS  ((size_t)NB*HWT*DD)
#define W_ELEMS   ((size_t)DD*DD)
// lf, gf, q, k, v, att, tmp, 4x(Whi,Wlo)
__device__ float g_scratch[LF_ELEMS + GF_ELEMS + LF_ELEMS + GF_ELEMS + GF_ELEMS +
                           LF_ELEMS + LF_ELEMS + 8 * W_ELEMS];

#define LN10K 9.210340371976184f

// ---------------------------------------------------------------------------
// PTX helpers
// ---------------------------------------------------------------------------
__device__ __forceinline__ void cp16(uint32_t dst, const void* src) {
    asm volatile("cp.async.cg.shared.global [%0], [%1], 16;\n" :: "r"(dst), "l"(src));
}
__device__ __forceinline__ uint32_t smem_u32(const void* p) {
    return (uint32_t)__cvta_generic_to_shared(p);
}
__device__ __forceinline__ void mma_tf32(float& c0, float& c1, float& c2, float& c3,
                                         const uint32_t a[4], uint32_t b0, uint32_t b1) {
    asm volatile(
        "mma.sync.aligned.m16n8k8.row.col.f32.tf32.tf32.f32 "
        "{%0,%1,%2,%3}, {%4,%5,%6,%7}, {%8,%9}, {%0,%1,%2,%3};\n"
        : "+f"(c0), "+f"(c1), "+f"(c2), "+f"(c3)
        : "r"(a[0]), "r"(a[1]), "r"(a[2]), "r"(a[3]), "r"(b0), "r"(b1));
}
__device__ __forceinline__ void mma_f16(float& c0, float& c1, float& c2, float& c3,
                                        uint32_t a0, uint32_t a1, uint32_t a2, uint32_t a3,
                                        uint32_t b0, uint32_t b1) {
    asm volatile(
        "mma.sync.aligned.m16n8k16.row.col.f32.f16.f16.f32 "
        "{%0,%1,%2,%3}, {%4,%5,%6,%7}, {%8,%9}, {%0,%1,%2,%3};\n"
        : "+f"(c0), "+f"(c1), "+f"(c2), "+f"(c3)
        : "r"(a0), "r"(a1), "r"(a2), "r"(a3), "r"(b0), "r"(b1));
}
__device__ __forceinline__ uint32_t pack_h2(float lo, float hi) {
    __half2 h = __floats2half2_rn(lo, hi);
    return *reinterpret_cast<uint32_t*>(&h);
}
__device__ __forceinline__ uint32_t to_tf32(float x) {
    uint32_t r;
    asm("cvt.rna.tf32.f32 %0, %1;" : "=r"(r) : "f"(x));
    return r;
}

// ---------------------------------------------------------------------------
// Positional encodings
// ---------------------------------------------------------------------------
__global__ void pe_local_kernel(const float* __restrict__ in, float* __restrict__ out) {
    int idx = blockIdx.x * blockDim.x + threadIdx.x;
    if (idx >= (int)LF_ELEMS) return;
    int d = idx & 255;
    int p = (idx >> 8) & (NP - 1);
    float div = expf((float)(d & ~1) * (-LN10K / 256.0f));
    float val;
    if ((d & 1) == 0) {
        float x = (float)(p & 31) * (1.0f / 31.0f);
        val = sinf(x * div);
    } else {
        float y = (float)(p >> 5) * (1.0f / 31.0f);
        val = cosf(y * div);
    }
    out[idx] = in[idx] + val;
}

__global__ __launch_bounds__(256) void pe_global_kernel(const float* __restrict__ in,
                                                        float* __restrict__ out) {
    __shared__ float tile[32][33];
    const int tx = threadIdx.x & 31;
    const int ty = threadIdx.x >> 5;
    const int t0 = blockIdx.x << 5;
    const int d0 = blockIdx.y << 5;
    const int b  = blockIdx.z;

    #pragma unroll
    for (int i = 0; i < 4; i++) {
        int d = d0 + ty + i * 8;
        tile[ty + i * 8][tx] = in[((size_t)b * DD + d) * HWT + t0 + tx];
    }
    __syncthreads();
    #pragma unroll
    for (int i = 0; i < 4; i++) {
        int t = t0 + ty + i * 8;
        int d = d0 + tx;
        float div = expf((float)(d & ~1) * (-LN10K / 256.0f));
        float val;
        if ((d & 1) == 0) {
            float x = (float)(t & 63) * (1.0f / 63.0f);
            val = sinf(x * div);
        } else {
            float y = (float)(t >> 6) * (1.0f / 63.0f);
            val = cosf(y * div);
        }
        out[((size_t)b * HWT + t) * DD + d] = tile[tx][ty + i * 8] + val;
    }
}

__global__ void add_kernel(const float* __restrict__ a, const float* __restrict__ b,
                           float* __restrict__ out) {
    int idx = blockIdx.x * blockDim.x + threadIdx.x;
    float4 x = ((const float4*)a)[idx];
    float4 y = ((const float4*)b)[idx];
    x.x += y.x; x.y += y.y; x.z += y.z; x.w += y.w;
    ((float4*)out)[idx] = x;
}

// Split W into tf32 hi/lo parts (one-time prep; W is 256x256)
__global__ void split_w_kernel(const float* __restrict__ W,
                               float* __restrict__ hi, float* __restrict__ lo) {
    int i = blockIdx.x * blockDim.x + threadIdx.x;
    float x = W[i];
    uint32_t h = to_tf32(x);
    hi[i] = __uint_as_float(h);
    lo[i] = __uint_as_float(to_tf32(x - __uint_as_float(h)));
}

// ---------------------------------------------------------------------------
// 3xTF32 GEMM: C[M,256] = A[M,256] @ W^T + bias  (fp32-grade accuracy)
// A split inline into hi/lo; W hi/lo precomputed. 3 MMAs per tile-step.
// ---------------------------------------------------------------------------
__global__ __launch_bounds__(256) void gemm_3xtf32_kernel(
    const float* __restrict__ A, const float* __restrict__ Whi,
    const float* __restrict__ Wlo, const float* __restrict__ bias,
    float* __restrict__ C)
{
    __shared__ float As [2][128][20];
    __shared__ float Wh_[2][128][20];
    __shared__ float Wl_[2][128][20];

    const int tid  = threadIdx.x;
    const int warp = tid >> 5;
    const int lane = tid & 31;
    const int gi = lane >> 2;
    const int ci = lane & 3;
    const int mBase = blockIdx.y << 7;
    const int nBase = blockIdx.x << 7;
    const int wm = (warp & 3) << 5;
    const int wn = (warp >> 2) << 6;

    float acc[2][8][4];
    #pragma unroll
    for (int mt = 0; mt < 2; mt++)
        #pragma unroll
        for (int nt = 0; nt < 8; nt++)
            #pragma unroll
            for (int i = 0; i < 4; i++) acc[mt][nt][i] = 0.0f;

    {
        #pragma unroll
        for (int j = 0; j < 2; j++) {
            int idx = tid * 2 + j;
            int r = idx >> 2, c = (idx & 3) * 4;
            cp16(smem_u32(&As [0][r][c]), A   + (size_t)(mBase + r) * 256 + c);
            cp16(smem_u32(&Wh_[0][r][c]), Whi + (size_t)(nBase + r) * 256 + c);
            cp16(smem_u32(&Wl_[0][r][c]), Wlo + (size_t)(nBase + r) * 256 + c);
        }
        asm volatile("cp.async.commit_group;\n");
    }

    for (int kt = 0; kt < 16; kt++) {
        const int buf = kt & 1;
        if (kt < 15) {
            const int nb_ = buf ^ 1;
            const int k0 = (kt + 1) * 16;
            #pragma unroll
            for (int j = 0; j < 2; j++) {
                int idx = tid * 2 + j;
                int r = idx >> 2, c = (idx & 3) * 4;
                cp16(smem_u32(&As [nb_][r][c]), A   + (size_t)(mBase + r) * 256 + k0 + c);
                cp16(smem_u32(&Wh_[nb_][r][c]), Whi + (size_t)(nBase + r) * 256 + k0 + c);
                cp16(smem_u32(&Wl_[nb_][r][c]), Wlo + (size_t)(nBase + r) * 256 + k0 + c);
            }
            asm volatile("cp.async.commit_group;\n");
            asm volatile("cp.async.wait_group 1;\n");
        } else {
            asm volatile("cp.async.wait_group 0;\n");
        }
        __syncthreads();

        #pragma unroll
        for (int ks = 0; ks < 2; ks++) {
            uint32_t ah[2][4], al[2][4];
            #pragma unroll
            for (int mt = 0; mt < 2; mt++) {
                #pragma unroll
                for (int r = 0; r < 4; r++) {
                    int row = wm + mt * 16 + gi + (r & 1) * 8;
                    int col = ks * 8 + ci + (r >> 1) * 4;
                    float x = As[buf][row][col];
                    uint32_t h = to_tf32(x);
                    ah[mt][r] = h;
                    al[mt][r] = to_tf32(x - __uint_as_float(h));
                }
            }
            #pragma unroll
            for (int nt = 0; nt < 8; nt++) {
                uint32_t bh0 = __float_as_uint(Wh_[buf][wn + nt * 8 + gi][ks * 8 + ci    ]);
                uint32_t bh1 = __float_as_uint(Wh_[buf][wn + nt * 8 + gi][ks * 8 + ci + 4]);
                uint32_t bl0 = __float_as_uint(Wl_[buf][wn + nt * 8 + gi][ks * 8 + ci    ]);
                uint32_t bl1 = __float_as_uint(Wl_[buf][wn + nt * 8 + gi][ks * 8 + ci + 4]);
                #pragma unroll
                for (int mt = 0; mt < 2; mt++) {
                    mma_tf32(acc[mt][nt][0], acc[mt][nt][1], acc[mt][nt][2], acc[mt][nt][3],
                             al[mt], bh0, bh1);
                    mma_tf32(acc[mt][nt][0], acc[mt][nt][1], acc[mt][nt][2], acc[mt][nt][3],
                             ah[mt], bl0, bl1);
                    mma_tf32(acc[mt][nt][0], acc[mt][nt][1], acc[mt][nt][2], acc[mt][nt][3],
                             ah[mt], bh0, bh1);
                }
            }
        }
        __syncthreads();
    }

    #pragma unroll
    for (int mt = 0; mt < 2; mt++) {
        #pragma unroll
        for (int nt = 0; nt < 8; nt++) {
            int ncol = nBase + wn + nt * 8 + 2 * ci;
            float2 bs = *(const float2*)(bias + ncol);
            int r0 = mBase + wm + mt * 16 + gi;
            float2 o0 = make_float2(acc[mt][nt][0] + bs.x, acc[mt][nt][1] + bs.y);
            float2 o1 = make_float2(acc[mt][nt][2] + bs.x, acc[mt][nt][3] + bs.y);
            *(float2*)(C + (size_t)r0 * 256 + ncol)       = o0;
            *(float2*)(C + (size_t)(r0 + 8) * 256 + ncol) = o1;
        }
    }
}

// ---------------------------------------------------------------------------
// Flash attention v2: 128 queries/block (4 warps x 32 rows = 2 m-tiles),
// KV tile 64 double-buffered. K and V converted once/tile to half2.
// QK^T and PV both f16 mma, fp32 accum + fp32 online softmax.
// ---------------------------------------------------------------------------
#define KPAD 36   // Ks/Vs fp32 row stride
#define KHP  20   // Kh row stride (u32) — conflict-free for B-frag reads
#define VHP  36   // Vh row stride (u32)

__global__ __launch_bounds__(128, 3) void flash_mma_kernel(
    const float* __restrict__ q, const float* __restrict__ k,
    const float* __restrict__ v, float* __restrict__ out)
{
    __shared__ float    Ks[2][64][KPAD];
    __shared__ float    Vs[2][64][KPAD];
    __shared__ uint32_t Kh[64][KHP];     // [key][dh/2]  half2
    __shared__ uint32_t Vh[32][VHP];     // [dh][key/2]  half2

    const int tid  = threadIdx.x;
    const int warp = tid >> 5;
    const int lane = tid & 31;
    const int gi = lane >> 2;
    const int ci = lane & 3;
    const int b = blockIdx.z;
    const int h = blockIdx.y;
    const int qbase = (blockIdx.x << 7) + warp * 32;

    // Q fragments (f16), scaled. Per m-tile, per k-step (16 dh each): 4 regs.
    uint32_t qh[2][2][4];
    {
        const float scale = 0.17677669529663687f;  // 1/sqrt(32)
        const float* qp = q + ((size_t)(b * NP + qbase)) * DD + h * DH;
        #pragma unroll
        for (int mt = 0; mt < 2; mt++) {
            #pragma unroll
            for (int s = 0; s < 2; s++) {
                #pragma unroll
                for (int r = 0; r < 4; r++) {
                    int row = mt * 16 + gi + (r & 1) * 8;
                    int col = s * 16 + 2 * ci + (r >> 1) * 8;
                    float2 t2 = *(const float2*)(qp + (size_t)row * DD + col);
                    qh[mt][s][r] = pack_h2(t2.x * scale, t2.y * scale);
                }
            }
        }
    }

    float O[2][4][4];
    #pragma unroll
    for (int mt = 0; mt < 2; mt++)
        #pragma unroll
        for (int n = 0; n < 4; n++)
            #pragma unroll
            for (int i = 0; i < 4; i++) O[mt][n][i] = 0.0f;
    float mM[2][2], lS[2][2];
    #pragma unroll
    for (int mt = 0; mt < 2; mt++) {
        mM[mt][0] = -1e30f; mM[mt][1] = -1e30f;
        lS[mt][0] = 0.0f;   lS[mt][1] = 0.0f;
    }

    const float* kbase = k + ((size_t)b * HWT) * DD + h * DH;
    const float* vbase = v + ((size_t)b * HWT) * DD + h * DH;

    {
        #pragma unroll
        for (int j = 0; j < 4; j++) {
            int idx = tid * 4 + j;
            int key = idx >> 3, ch = idx & 7;
            cp16(smem_u32(&Ks[0][key][ch * 4]), kbase + (size_t)key * DD + ch * 4);
            cp16(smem_u32(&Vs[0][key][ch * 4]), vbase + (size_t)key * DD + ch * 4);
        }
        asm volatile("cp.async.commit_group;\n");
    }

    for (int t = 0; t < 64; t++) {
        const int buf = t & 1;
        if (t < 63) {
            const int nb_ = buf ^ 1;
            const size_t kv0 = (size_t)(t + 1) << 6;
            #pragma unroll
            for (int j = 0; j < 4; j++) {
                int idx = tid * 4 + j;
                int key = idx >> 3, ch = idx & 7;
                cp16(smem_u32(&Ks[nb_][key][ch * 4]), kbase + (kv0 + key) * DD + ch * 4);
                cp16(smem_u32(&Vs[nb_][key][ch * 4]), vbase + (kv0 + key) * DD + ch * 4);
            }
            asm volatile("cp.async.commit_group;\n");
            asm volatile("cp.async.wait_group 1;\n");
        } else {
            asm volatile("cp.async.wait_group 0;\n");
        }
        __syncthreads();   // S1: tile visible; prior Kh/Vh consumers done

        // cooperative convert: K -> Kh[key][dh/2], V -> Vh[dh][key/2]
        #pragma unroll
        for (int j = 0; j < 8; j++) {
            int idx = tid + j * 128;         // 0..1023
            int key = idx >> 4, jc = idx & 15;
            float2 kk = *(const float2*)(&Ks[buf][key][2 * jc]);
            Kh[key][jc] = pack_h2(kk.x, kk.y);
        }
        #pragma unroll
        for (int j = 0; j < 8; j++) {
            int k2 = warp * 8 + j;
            Vh[lane][k2] = pack_h2(Vs[buf][2 * k2][lane], Vs[buf][2 * k2 + 1][lane]);
        }
        __syncthreads();   // S2: converts visible

        #pragma unroll
        for (int mt = 0; mt < 2; mt++) {
            // ---- S = Q K^T (f16), 8 n-tiles x 2 k-steps ----
            float Sf[8][4];
            #pragma unroll
            for (int nt = 0; nt < 8; nt++) {
                float c0 = 0.f, c1 = 0.f, c2 = 0.f, c3 = 0.f;
                #pragma unroll
                for (int s = 0; s < 2; s++) {
                    uint32_t b0 = Kh[nt * 8 + gi][s * 8 + ci];
                    uint32_t b1 = Kh[nt * 8 + gi][s * 8 + ci + 4];
                    mma_f16(c0, c1, c2, c3,
                            qh[mt][s][0], qh[mt][s][1], qh[mt][s][2], qh[mt][s][3],
                            b0, b1);
                }
                Sf[nt][0] = c0; Sf[nt][1] = c1; Sf[nt][2] = c2; Sf[nt][3] = c3;
            }

            // ---- online softmax ----
            float mx0 = -1e30f, mx1 = -1e30f;
            #pragma unroll
            for (int nt = 0; nt < 8; nt++) {
                mx0 = fmaxf(mx0, fmaxf(Sf[nt][0], Sf[nt][1]));
                mx1 = fmaxf(mx1, fmaxf(Sf[nt][2], Sf[nt][3]));
            }
            mx0 = fmaxf(mx0, __shfl_xor_sync(0xffffffffu, mx0, 1));
            mx0 = fmaxf(mx0, __shfl_xor_sync(0xffffffffu, mx0, 2));
            mx1 = fmaxf(mx1, __shfl_xor_sync(0xffffffffu, mx1, 1));
            mx1 = fmaxf(mx1, __shfl_xor_sync(0xffffffffu, mx1, 2));

            float mn0 = fmaxf(mM[mt][0], mx0), mn1 = fmaxf(mM[mt][1], mx1);
            float corr0 = __expf(mM[mt][0] - mn0), corr1 = __expf(mM[mt][1] - mn1);
            float sum0 = 0.f, sum1 = 0.f;
            #pragma unroll
            for (int nt = 0; nt < 8; nt++) {
                Sf[nt][0] = __expf(Sf[nt][0] - mn0); sum0 += Sf[nt][0];
                Sf[nt][1] = __expf(Sf[nt][1] - mn0); sum0 += Sf[nt][1];
                Sf[nt][2] = __expf(Sf[nt][2] - mn1); sum1 += Sf[nt][2];
                Sf[nt][3] = __expf(Sf[nt][3] - mn1); sum1 += Sf[nt][3];
            }
            sum0 += __shfl_xor_sync(0xffffffffu, sum0, 1);
            sum0 += __shfl_xor_sync(0xffffffffu, sum0, 2);
            sum1 += __shfl_xor_sync(0xffffffffu, sum1, 1);
            sum1 += __shfl_xor_sync(0xffffffffu, sum1, 2);
            lS[mt][0] = lS[mt][0] * corr0 + sum0;
            lS[mt][1] = lS[mt][1] * corr1 + sum1;
            mM[mt][0] = mn0; mM[mt][1] = mn1;

            #pragma unroll
            for (int n = 0; n < 4; n++) {
                O[mt][n][0] *= corr0; O[mt][n][1] *= corr0;
                O[mt][n][2] *= corr1; O[mt][n][3] *= corr1;
            }

            // ---- O += P V (f16): 4 k-steps x 4 n-tiles ----
            #pragma unroll
            for (int s = 0; s < 4; s++) {
                uint32_t a0 = pack_h2(Sf[2 * s][0],     Sf[2 * s][1]);
                uint32_t a1 = pack_h2(Sf[2 * s][2],     Sf[2 * s][3]);
                uint32_t a2 = pack_h2(Sf[2 * s + 1][0], Sf[2 * s + 1][1]);
                uint32_t a3 = pack_h2(Sf[2 * s + 1][2], Sf[2 * s + 1][3]);
                #pragma unroll
                for (int n = 0; n < 4; n++) {
                    int col = n * 8 + gi;
                    uint32_t b0 = Vh[col][s * 8 + ci];
                    uint32_t b1 = Vh[col][s * 8 + ci + 4];
                    mma_f16(O[mt][n][0], O[mt][n][1], O[mt][n][2], O[mt][n][3],
                            a0, a1, a2, a3, b0, b1);
                }
            }
        }
    }

    float* op = out + ((size_t)(b * NP + qbase)) * DD + h * DH;
    #pragma unroll
    for (int mt = 0; mt < 2; mt++) {
        float inv0 = 1.0f / lS[mt][0], inv1 = 1.0f / lS[mt][1];
        #pragma unroll
        for (int n = 0; n < 4; n++) {
            float2 r0 = make_float2(O[mt][n][0] * inv0, O[mt][n][1] * inv0);
            float2 r1 = make_float2(O[mt][n][2] * inv1, O[mt][n][3] * inv1);
            *(float2*)(op + (size_t)(mt * 16 + gi) * DD     + n * 8 + 2 * ci) = r0;
            *(float2*)(op + (size_t)(mt * 16 + gi + 8) * DD + n * 8 + 2 * ci) = r1;
        }
    }
}

// ---------------------------------------------------------------------------
extern "C" void kernel_launch(void* const* d_in, const int* in_sizes, int n_in,
                              void* d_out, int out_size) {
    const float* local_feat  = (const float*)d_in[0];
    const float* global_feat = (const float*)d_in[1];
    const float* Wq = (const float*)d_in[2];
    const float* bq = (const float*)d_in[3];
    const float* Wk = (const float*)d_in[4];
    const float* bk = (const float*)d_in[5];
    const float* Wv = (const float*)d_in[6];
    const float* bv = (const float*)d_in[7];
    const float* Wo = (const float*)d_in[8];
    const float* bo = (const float*)d_in[9];
    float* out = (float*)d_out;

    float* base = nullptr;
    cudaGetSymbolAddress((void**)&base, g_scratch);
    float* lf   = base;
    float* gf   = lf   + LF_ELEMS;
    float* q    = gf   + GF_ELEMS;
    float* k    = q    + LF_ELEMS;
    float* v    = k    + GF_ELEMS;
    float* att  = v    + GF_ELEMS;
    float* tmp  = att  + LF_ELEMS;
    float* wqh  = tmp  + LF_ELEMS;  float* wql = wqh + W_ELEMS;
    float* wkh  = wql  + W_ELEMS;   float* wkl = wkh + W_ELEMS;
    float* wvh  = wkl  + W_ELEMS;   float* wvl = wvh + W_ELEMS;
    float* woh  = wvl  + W_ELEMS;   float* wol = woh + W_ELEMS;

    split_w_kernel<<<(int)(W_ELEMS / 256), 256>>>(Wq, wqh, wql);
    split_w_kernel<<<(int)(W_ELEMS / 256), 256>>>(Wk, wkh, wkl);
    split_w_kernel<<<(int)(W_ELEMS / 256), 256>>>(Wv, wvh, wvl);
    split_w_kernel<<<(int)(W_ELEMS / 256), 256>>>(Wo, woh, wol);

    pe_local_kernel<<<(int)(LF_ELEMS / 256), 256>>>(local_feat, lf);
    pe_global_kernel<<<dim3(HWT / 32, DD / 32, NB), 256>>>(global_feat, gf);

    gemm_3xtf32_kernel<<<dim3(2, (NB * NP)  / 128), 256>>>(lf, wqh, wql, bq, q);
    gemm_3xtf32_kernel<<<dim3(2, (NB * HWT) / 128), 256>>>(gf, wkh, wkl, bk, k);
    gemm_3xtf32_kernel<<<dim3(2, (NB * HWT) / 128), 256>>>(gf, wvh, wvl, bv, v);

    flash_mma_kernel<<<dim3(NP / 128, HEADS, NB), 128>>>(q, k, v, att);

    add_kernel<<<(int)(LF_ELEMS / 1024), 256>>>(lf, att, tmp);
    gemm_3xtf32_kernel<<<dim3(2, (NB * NP) / 128), 256>>>(tmp, woh, wol, bo, out);
}

// round 8
// speedup vs baseline: 1.2823x; 1.2823x over previous
#include <cuda_runtime.h>
#include <cuda_fp16.h>
#include <cuda_bf16.h>
#include <stdint.h>
#include <stddef.h>
#include <math.h>

#define NB   4
#define NP   1024
#define DD   256
#define HWT  4096
#define HEADS 8
#define DH   32

#define LF_ELEMS  ((size_t)NB*NP*DD)   // 1M
#define GF_ELEMS  ((size_t)NB*HWT*DD)  // 4M
// floats: lf(1M) q(1M) k(4M) v(4M); u32: lf hi/lo(1M) gf hi/lo(4M) tmp hi/lo(1M) w(256K)
__device__ float g_scratch[17 * 1024 * 1024];

#define LN10K 9.210340371976184f

// ---------------------------------------------------------------------------
// helpers
// ---------------------------------------------------------------------------
__device__ __forceinline__ void cp16(uint32_t dst, const void* src) {
    asm volatile("cp.async.cg.shared.global [%0], [%1], 16;\n" :: "r"(dst), "l"(src));
}
__device__ __forceinline__ uint32_t smem_u32(const void* p) {
    return (uint32_t)__cvta_generic_to_shared(p);
}
__device__ __forceinline__ void mma_bf16(float& c0, float& c1, float& c2, float& c3,
                                         const uint32_t a[4], uint32_t b0, uint32_t b1) {
    asm volatile(
        "mma.sync.aligned.m16n8k16.row.col.f32.bf16.bf16.f32 "
        "{%0,%1,%2,%3}, {%4,%5,%6,%7}, {%8,%9}, {%0,%1,%2,%3};\n"
        : "+f"(c0), "+f"(c1), "+f"(c2), "+f"(c3)
        : "r"(a[0]), "r"(a[1]), "r"(a[2]), "r"(a[3]), "r"(b0), "r"(b1));
}
__device__ __forceinline__ void mma_f16(float& c0, float& c1, float& c2, float& c3,
                                        uint32_t a0, uint32_t a1, uint32_t a2, uint32_t a3,
                                        uint32_t b0, uint32_t b1) {
    asm volatile(
        "mma.sync.aligned.m16n8k16.row.col.f32.f16.f16.f32 "
        "{%0,%1,%2,%3}, {%4,%5,%6,%7}, {%8,%9}, {%0,%1,%2,%3};\n"
        : "+f"(c0), "+f"(c1), "+f"(c2), "+f"(c3)
        : "r"(a0), "r"(a1), "r"(a2), "r"(a3), "r"(b0), "r"(b1));
}
__device__ __forceinline__ uint32_t pack_h2(float lo, float hi) {
    __half2 h = __floats2half2_rn(lo, hi);
    return *reinterpret_cast<uint32_t*>(&h);
}
// split (a,b) into packed-bf16 hi and lo words (element a in low 16 bits)
__device__ __forceinline__ void split_pack_bf2(float a, float b, uint32_t& hi, uint32_t& lo) {
    __nv_bfloat16 ah = __float2bfloat16_rn(a);
    __nv_bfloat16 bh = __float2bfloat16_rn(b);
    float ar = a - __bfloat162float(ah);
    float br = b - __bfloat162float(bh);
    __nv_bfloat162 h2 = __halves2bfloat162(ah, bh);
    __nv_bfloat162 l2 = __floats2bfloat162_rn(ar, br);
    hi = *reinterpret_cast<uint32_t*>(&h2);
    lo = *reinterpret_cast<uint32_t*>(&l2);
}

// ---------------------------------------------------------------------------
// PE local: lf = local_feat + PE (fp32) AND packed bf16 hi/lo
// ---------------------------------------------------------------------------
__global__ void pe_local_kernel(const float* __restrict__ in, float* __restrict__ lf,
                                uint32_t* __restrict__ lfhi, uint32_t* __restrict__ lflo) {
    int idx = blockIdx.x * blockDim.x + threadIdx.x;   // pair index
    if (idx >= (int)(LF_ELEMS / 2)) return;
    int d2 = idx & 127;          // pair within row
    int p  = (idx >> 7) & (NP - 1);
    int d  = 2 * d2;
    float div = expf((float)d * (-LN10K / 256.0f));
    float x = (float)(p & 31) * (1.0f / 31.0f);
    float y = (float)(p >> 5) * (1.0f / 31.0f);
    float2 v = *(const float2*)(in + (size_t)idx * 2);
    float v0 = v.x + sinf(x * div);
    float v1 = v.y + cosf(y * div);
    *(float2*)(lf + (size_t)idx * 2) = make_float2(v0, v1);
    uint32_t hi, lo;
    split_pack_bf2(v0, v1, hi, lo);
    lfhi[idx] = hi;
    lflo[idx] = lo;
}

// ---------------------------------------------------------------------------
// PE global: transpose (NB,DD,HWT) -> (NB,HWT,DD) + PE; packed bf16 hi/lo only
// ---------------------------------------------------------------------------
__global__ __launch_bounds__(256) void pe_global_kernel(const float* __restrict__ in,
                                                        uint32_t* __restrict__ gfhi,
                                                        uint32_t* __restrict__ gflo) {
    __shared__ float tile[32][33];
    const int tid = threadIdx.x;
    const int tx = tid & 31;
    const int ty = tid >> 5;
    const int t0 = blockIdx.x << 5;
    const int d0 = blockIdx.y << 5;
    const int b  = blockIdx.z;

    #pragma unroll
    for (int i = 0; i < 4; i++) {
        int d = d0 + ty + i * 8;
        tile[ty + i * 8][tx] = in[((size_t)b * DD + d) * HWT + t0 + tx];
    }
    __syncthreads();

    const int dp = tid & 15;         // d-pair 0..15
    #pragma unroll
    for (int i = 0; i < 2; i++) {
        int tr = (tid >> 4) + i * 16;   // 0..31
        int t = t0 + tr;
        int d = d0 + 2 * dp;
        float div = expf((float)d * (-LN10K / 256.0f));
        float x = (float)(t & 63) * (1.0f / 63.0f);
        float y = (float)(t >> 6) * (1.0f / 63.0f);
        float v0 = tile[2 * dp][tr]     + sinf(x * div);
        float v1 = tile[2 * dp + 1][tr] + cosf(y * div);
        uint32_t hi, lo;
        split_pack_bf2(v0, v1, hi, lo);
        size_t o = ((size_t)b * HWT + t) * 128 + d0 / 2 + dp;
        gfhi[o] = hi;
        gflo[o] = lo;
    }
}

// ---------------------------------------------------------------------------
// Split all 4 weight matrices into packed bf16 hi/lo: [n][k/2] u32
// ---------------------------------------------------------------------------
__global__ void split_w_kernel(const float* __restrict__ W0, const float* __restrict__ W1,
                               const float* __restrict__ W2, const float* __restrict__ W3,
                               uint32_t* __restrict__ out) {   // 4 x (hi 32768, lo 32768)
    int idx = blockIdx.x * blockDim.x + threadIdx.x;   // 0..32767 pair
    int m = blockIdx.y;
    const float* W = (m == 0) ? W0 : (m == 1) ? W1 : (m == 2) ? W2 : W3;
    float2 v = *(const float2*)(W + (size_t)idx * 2);
    uint32_t hi, lo;
    split_pack_bf2(v.x, v.y, hi, lo);
    out[(size_t)m * 65536 + idx]         = hi;
    out[(size_t)m * 65536 + 32768 + idx] = lo;
}

// ---------------------------------------------------------------------------
// bf16x3 GEMM: C[M,256] = A @ W^T + bias, fp32-grade accuracy.
// A, W given as packed-bf16 hi/lo [rows][128] u32. 128x128 tile, 8 warps,
// BK=16 (8 u32) double-buffered cp.async; 3 MMAs (hh, hl, lh) per step.
// smem row stride 12 u32 (48B): 16B-aligned for cp.async, conflict-free LDS.
// ---------------------------------------------------------------------------
__global__ __launch_bounds__(256) void gemm_bf16x3_kernel(
    const uint32_t* __restrict__ Ahi, const uint32_t* __restrict__ Alo,
    const uint32_t* __restrict__ Whi, const uint32_t* __restrict__ Wlo,
    const float* __restrict__ bias, float* __restrict__ C)
{
    __shared__ uint32_t sAh[2][128][12];
    __shared__ uint32_t sAl[2][128][12];
    __shared__ uint32_t sWh[2][128][12];
    __shared__ uint32_t sWl[2][128][12];

    const int tid  = threadIdx.x;
    const int warp = tid >> 5;
    const int lane = tid & 31;
    const int gi = lane >> 2;
    const int ci = lane & 3;
    const int mBase = blockIdx.y << 7;
    const int nBase = blockIdx.x << 7;
    const int wm = (warp & 3) << 5;
    const int wn = (warp >> 2) << 6;

    // cp.async assignment: arr = tid>>6 (0:Ah 1:Al 2:Wh 3:Wl), rows (tid&63)*2, +1
    const int arr = tid >> 6;
    const int r0 = (tid & 63) * 2;
    const uint32_t* gsrc = (arr == 0) ? Ahi + (size_t)mBase * 128
                         : (arr == 1) ? Alo + (size_t)mBase * 128
                         : (arr == 2) ? Whi + (size_t)nBase * 128
                                      : Wlo + (size_t)nBase * 128;
    uint32_t sdst = (arr == 0) ? smem_u32(&sAh[0][0][0])
                  : (arr == 1) ? smem_u32(&sAl[0][0][0])
                  : (arr == 2) ? smem_u32(&sWh[0][0][0])
                               : smem_u32(&sWl[0][0][0]);
    const uint32_t stageBytes = 128 * 12 * 4;

    float acc[2][8][4];
    #pragma unroll
    for (int mt = 0; mt < 2; mt++)
        #pragma unroll
        for (int nt = 0; nt < 8; nt++)
            #pragma unroll
            for (int i = 0; i < 4; i++) acc[mt][nt][i] = 0.0f;

    // prefetch k-tile 0
    #pragma unroll
    for (int j = 0; j < 4; j++) {
        int row = r0 + (j >> 1), half = j & 1;
        cp16(sdst + (row * 12 + half * 4) * 4, gsrc + (size_t)row * 128 + half * 4);
    }
    asm volatile("cp.async.commit_group;\n");

    for (int kt = 0; kt < 16; kt++) {
        const int buf = kt & 1;
        if (kt < 15) {
            const int k0u = (kt + 1) * 8;
            uint32_t d2 = sdst + (buf ^ 1) * stageBytes;
            #pragma unroll
            for (int j = 0; j < 4; j++) {
                int row = r0 + (j >> 1), half = j & 1;
                cp16(d2 + (row * 12 + half * 4) * 4, gsrc + (size_t)row * 128 + k0u + half * 4);
            }
            asm volatile("cp.async.commit_group;\n");
            asm volatile("cp.async.wait_group 1;\n");
        } else {
            asm volatile("cp.async.wait_group 0;\n");
        }
        __syncthreads();

        uint32_t ah[2][4], al[2][4];
        #pragma unroll
        for (int mt = 0; mt < 2; mt++) {
            int rA = wm + mt * 16 + gi;
            ah[mt][0] = sAh[buf][rA    ][ci    ];
            ah[mt][1] = sAh[buf][rA + 8][ci    ];
            ah[mt][2] = sAh[buf][rA    ][ci + 4];
            ah[mt][3] = sAh[buf][rA + 8][ci + 4];
            al[mt][0] = sAl[buf][rA    ][ci    ];
            al[mt][1] = sAl[buf][rA + 8][ci    ];
            al[mt][2] = sAl[buf][rA    ][ci + 4];
            al[mt][3] = sAl[buf][rA + 8][ci + 4];
        }
        #pragma unroll
        for (int nt = 0; nt < 8; nt++) {
            int rW = wn + nt * 8 + gi;
            uint32_t bh0 = sWh[buf][rW][ci    ];
            uint32_t bh1 = sWh[buf][rW][ci + 4];
            uint32_t bl0 = sWl[buf][rW][ci    ];
            uint32_t bl1 = sWl[buf][rW][ci + 4];
            #pragma unroll
            for (int mt = 0; mt < 2; mt++) {
                mma_bf16(acc[mt][nt][0], acc[mt][nt][1], acc[mt][nt][2], acc[mt][nt][3],
                         al[mt], bh0, bh1);
                mma_bf16(acc[mt][nt][0], acc[mt][nt][1], acc[mt][nt][2], acc[mt][nt][3],
                         ah[mt], bl0, bl1);
                mma_bf16(acc[mt][nt][0], acc[mt][nt][1], acc[mt][nt][2], acc[mt][nt][3],
                         ah[mt], bh0, bh1);
            }
        }
        __syncthreads();
    }

    #pragma unroll
    for (int mt = 0; mt < 2; mt++) {
        #pragma unroll
        for (int nt = 0; nt < 8; nt++) {
            int ncol = nBase + wn + nt * 8 + 2 * ci;
            float2 bs = *(const float2*)(bias + ncol);
            int row = mBase + wm + mt * 16 + gi;
            float2 o0 = make_float2(acc[mt][nt][0] + bs.x, acc[mt][nt][1] + bs.y);
            float2 o1 = make_float2(acc[mt][nt][2] + bs.x, acc[mt][nt][3] + bs.y);
            *(float2*)(C + (size_t)row * 256 + ncol)       = o0;
            *(float2*)(C + (size_t)(row + 8) * 256 + ncol) = o1;
        }
    }
}

// ---------------------------------------------------------------------------
// Flash attention: 128 queries/block (4 warps x 32 rows = 2 m-tiles),
// KV tile 64 double-buffered, f16 mma for QK^T and PV, fp32 softmax.
// Epilogue fuses residual add (lf) and emits packed bf16 hi/lo for O-gemm.
// ---------------------------------------------------------------------------
#define KPAD 36
#define KHP  20
#define VHP  36

__global__ __launch_bounds__(128, 3) void flash_mma_kernel(
    const float* __restrict__ q, const float* __restrict__ k,
    const float* __restrict__ v, const float* __restrict__ lf,
    uint32_t* __restrict__ tmphi, uint32_t* __restrict__ tmplo)
{
    __shared__ float    Ks[2][64][KPAD];
    __shared__ float    Vs[2][64][KPAD];
    __shared__ uint32_t Kh[64][KHP];
    __shared__ uint32_t Vh[32][VHP];

    const int tid  = threadIdx.x;
    const int warp = tid >> 5;
    const int lane = tid & 31;
    const int gi = lane >> 2;
    const int ci = lane & 3;
    const int b = blockIdx.z;
    const int h = blockIdx.y;
    const int qbase = (blockIdx.x << 7) + warp * 32;

    uint32_t qh[2][2][4];
    {
        const float scale = 0.17677669529663687f;  // 1/sqrt(32)
        const float* qp = q + ((size_t)(b * NP + qbase)) * DD + h * DH;
        #pragma unroll
        for (int mt = 0; mt < 2; mt++)
            #pragma unroll
            for (int s = 0; s < 2; s++)
                #pragma unroll
                for (int r = 0; r < 4; r++) {
                    int row = mt * 16 + gi + (r & 1) * 8;
                    int col = s * 16 + 2 * ci + (r >> 1) * 8;
                    float2 t2 = *(const float2*)(qp + (size_t)row * DD + col);
                    qh[mt][s][r] = pack_h2(t2.x * scale, t2.y * scale);
                }
    }

    float O[2][4][4];
    #pragma unroll
    for (int mt = 0; mt < 2; mt++)
        #pragma unroll
        for (int n = 0; n < 4; n++)
            #pragma unroll
            for (int i = 0; i < 4; i++) O[mt][n][i] = 0.0f;
    float mM[2][2], lS[2][2];
    #pragma unroll
    for (int mt = 0; mt < 2; mt++) {
        mM[mt][0] = -1e30f; mM[mt][1] = -1e30f;
        lS[mt][0] = 0.0f;   lS[mt][1] = 0.0f;
    }

    const float* kbase = k + ((size_t)b * HWT) * DD + h * DH;
    const float* vbase = v + ((size_t)b * HWT) * DD + h * DH;

    {
        #pragma unroll
        for (int j = 0; j < 4; j++) {
            int idx = tid * 4 + j;
            int key = idx >> 3, ch = idx & 7;
            cp16(smem_u32(&Ks[0][key][ch * 4]), kbase + (size_t)key * DD + ch * 4);
            cp16(smem_u32(&Vs[0][key][ch * 4]), vbase + (size_t)key * DD + ch * 4);
        }
        asm volatile("cp.async.commit_group;\n");
    }

    for (int t = 0; t < 64; t++) {
        const int buf = t & 1;
        if (t < 63) {
            const int nb_ = buf ^ 1;
            const size_t kv0 = (size_t)(t + 1) << 6;
            #pragma unroll
            for (int j = 0; j < 4; j++) {
                int idx = tid * 4 + j;
                int key = idx >> 3, ch = idx & 7;
                cp16(smem_u32(&Ks[nb_][key][ch * 4]), kbase + (kv0 + key) * DD + ch * 4);
                cp16(smem_u32(&Vs[nb_][key][ch * 4]), vbase + (kv0 + key) * DD + ch * 4);
            }
            asm volatile("cp.async.commit_group;\n");
            asm volatile("cp.async.wait_group 1;\n");
        } else {
            asm volatile("cp.async.wait_group 0;\n");
        }
        __syncthreads();

        #pragma unroll
        for (int j = 0; j < 8; j++) {
            int idx = tid + j * 128;
            int key = idx >> 4, jc = idx & 15;
            float2 kk = *(const float2*)(&Ks[buf][key][2 * jc]);
            Kh[key][jc] = pack_h2(kk.x, kk.y);
        }
        #pragma unroll
        for (int j = 0; j < 8; j++) {
            int k2 = warp * 8 + j;
            Vh[lane][k2] = pack_h2(Vs[buf][2 * k2][lane], Vs[buf][2 * k2 + 1][lane]);
        }
        __syncthreads();

        #pragma unroll
        for (int mt = 0; mt < 2; mt++) {
            float Sf[8][4];
            #pragma unroll
            for (int nt = 0; nt < 8; nt++) {
                float c0 = 0.f, c1 = 0.f, c2 = 0.f, c3 = 0.f;
                #pragma unroll
                for (int s = 0; s < 2; s++) {
                    uint32_t b0 = Kh[nt * 8 + gi][s * 8 + ci];
                    uint32_t b1 = Kh[nt * 8 + gi][s * 8 + ci + 4];
                    mma_f16(c0, c1, c2, c3,
                            qh[mt][s][0], qh[mt][s][1], qh[mt][s][2], qh[mt][s][3],
                            b0, b1);
                }
                Sf[nt][0] = c0; Sf[nt][1] = c1; Sf[nt][2] = c2; Sf[nt][3] = c3;
            }

            float mx0 = -1e30f, mx1 = -1e30f;
            #pragma unroll
            for (int nt = 0; nt < 8; nt++) {
                mx0 = fmaxf(mx0, fmaxf(Sf[nt][0], Sf[nt][1]));
                mx1 = fmaxf(mx1, fmaxf(Sf[nt][2], Sf[nt][3]));
            }
            mx0 = fmaxf(mx0, __shfl_xor_sync(0xffffffffu, mx0, 1));
            mx0 = fmaxf(mx0, __shfl_xor_sync(0xffffffffu, mx0, 2));
            mx1 = fmaxf(mx1, __shfl_xor_sync(0xffffffffu, mx1, 1));
            mx1 = fmaxf(mx1, __shfl_xor_sync(0xffffffffu, mx1, 2));

            float mn0 = fmaxf(mM[mt][0], mx0), mn1 = fmaxf(mM[mt][1], mx1);
            float corr0 = __expf(mM[mt][0] - mn0), corr1 = __expf(mM[mt][1] - mn1);
            float sum0 = 0.f, sum1 = 0.f;
            #pragma unroll
            for (int nt = 0; nt < 8; nt++) {
                Sf[nt][0] = __expf(Sf[nt][0] - mn0); sum0 += Sf[nt][0];
                Sf[nt][1] = __expf(Sf[nt][1] - mn0); sum0 += Sf[nt][1];
                Sf[nt][2] = __expf(Sf[nt][2] - mn1); sum1 += Sf[nt][2];
                Sf[nt][3] = __expf(Sf[nt][3] - mn1); sum1 += Sf[nt][3];
            }
            sum0 += __shfl_xor_sync(0xffffffffu, sum0, 1);
            sum0 += __shfl_xor_sync(0xffffffffu, sum0, 2);
            sum1 += __shfl_xor_sync(0xffffffffu, sum1, 1);
            sum1 += __shfl_xor_sync(0xffffffffu, sum1, 2);
            lS[mt][0] = lS[mt][0] * corr0 + sum0;
            lS[mt][1] = lS[mt][1] * corr1 + sum1;
            mM[mt][0] = mn0; mM[mt][1] = mn1;

            #pragma unroll
            for (int n = 0; n < 4; n++) {
                O[mt][n][0] *= corr0; O[mt][n][1] *= corr0;
                O[mt][n][2] *= corr1; O[mt][n][3] *= corr1;
            }

            #pragma unroll
            for (int s = 0; s < 4; s++) {
                uint32_t a0 = pack_h2(Sf[2 * s][0],     Sf[2 * s][1]);
                uint32_t a1 = pack_h2(Sf[2 * s][2],     Sf[2 * s][3]);
                uint32_t a2 = pack_h2(Sf[2 * s + 1][0], Sf[2 * s + 1][1]);
                uint32_t a3 = pack_h2(Sf[2 * s + 1][2], Sf[2 * s + 1][3]);
                #pragma unroll
                for (int n = 0; n < 4; n++) {
                    int col = n * 8 + gi;
                    uint32_t b0 = Vh[col][s * 8 + ci];
                    uint32_t b1 = Vh[col][s * 8 + ci + 4];
                    mma_f16(O[mt][n][0], O[mt][n][1], O[mt][n][2], O[mt][n][3],
                            a0, a1, a2, a3, b0, b1);
                }
            }
        }
    }

    // Epilogue: out = O/l + lf, packed bf16 hi/lo for the O-projection GEMM
    const float* lfp = lf + ((size_t)(b * NP + qbase)) * DD + h * DH;
    uint32_t* th = tmphi + ((size_t)(b * NP + qbase)) * 128 + h * (DH / 2);
    uint32_t* tl = tmplo + ((size_t)(b * NP + qbase)) * 128 + h * (DH / 2);
    #pragma unroll
    for (int mt = 0; mt < 2; mt++) {
        float inv0 = 1.0f / lS[mt][0], inv1 = 1.0f / lS[mt][1];
        #pragma unroll
        for (int n = 0; n < 4; n++) {
            int row0 = mt * 16 + gi, row1 = row0 + 8;
            int col = n * 8 + 2 * ci;
            float2 L0 = *(const float2*)(lfp + (size_t)row0 * DD + col);
            float2 L1 = *(const float2*)(lfp + (size_t)row1 * DD + col);
            float a0 = O[mt][n][0] * inv0 + L0.x;
            float a1 = O[mt][n][1] * inv0 + L0.y;
            float b0 = O[mt][n][2] * inv1 + L1.x;
            float b1 = O[mt][n][3] * inv1 + L1.y;
            uint32_t hi, lo;
            split_pack_bf2(a0, a1, hi, lo);
            th[(size_t)row0 * 128 + col / 2] = hi;
            tl[(size_t)row0 * 128 + col / 2] = lo;
            split_pack_bf2(b0, b1, hi, lo);
            th[(size_t)row1 * 128 + col / 2] = hi;
            tl[(size_t)row1 * 128 + col / 2] = lo;
        }
    }
}

// ---------------------------------------------------------------------------
extern "C" void kernel_launch(void* const* d_in, const int* in_sizes, int n_in,
                              void* d_out, int out_size) {
    const float* local_feat  = (const float*)d_in[0];
    const float* global_feat = (const float*)d_in[1];
    const float* Wq = (const float*)d_in[2];
    const float* bq = (const float*)d_in[3];
    const float* Wk = (const float*)d_in[4];
    const float* bk = (const float*)d_in[5];
    const float* Wv = (const float*)d_in[6];
    const float* bv = (const float*)d_in[7];
    const float* Wo = (const float*)d_in[8];
    const float* bo = (const float*)d_in[9];
    float* out = (float*)d_out;

    float* base = nullptr;
    cudaGetSymbolAddress((void**)&base, g_scratch);
    float* lf = base;                        // LF
    float* q  = lf + LF_ELEMS;               // LF
    float* k  = q  + LF_ELEMS;               // GF
    float* v  = k  + GF_ELEMS;               // GF
    uint32_t* lfhi  = (uint32_t*)(v + GF_ELEMS);   // LF/2
    uint32_t* lflo  = lfhi  + LF_ELEMS / 2;
    uint32_t* gfhi  = lflo  + LF_ELEMS / 2;        // GF/2
    uint32_t* gflo  = gfhi  + GF_ELEMS / 2;
    uint32_t* tmphi = gflo  + GF_ELEMS / 2;        // LF/2
    uint32_t* tmplo = tmphi + LF_ELEMS / 2;
    uint32_t* wsp   = tmplo + LF_ELEMS / 2;        // 4 * 65536
    uint32_t* wqh = wsp;               uint32_t* wql = wsp + 32768;
    uint32_t* wkh = wsp + 65536;       uint32_t* wkl = wsp + 65536 + 32768;
    uint32_t* wvh = wsp + 131072;      uint32_t* wvl = wsp + 131072 + 32768;
    uint32_t* woh = wsp + 196608;      uint32_t* wol = wsp + 196608 + 32768;

    split_w_kernel<<<dim3(128, 4), 256>>>(Wq, Wk, Wv, Wo, wsp);
    pe_local_kernel<<<(int)(LF_ELEMS / 2 / 256), 256>>>(local_feat, lf, lfhi, lflo);
    pe_global_kernel<<<dim3(HWT / 32, DD / 32, NB), 256>>>(global_feat, gfhi, gflo);

    gemm_bf16x3_kernel<<<dim3(2, (NB * NP)  / 128), 256>>>(lfhi, lflo, wqh, wql, bq, q);
    gemm_bf16x3_kernel<<<dim3(2, (NB * HWT) / 128), 256>>>(gfhi, gflo, wkh, wkl, bk, k);
    gemm_bf16x3_kernel<<<dim3(2, (NB * HWT) / 128), 256>>>(gfhi, gflo, wvh, wvl, bv, v);

    flash_mma_kernel<<<dim3(NP / 128, HEADS, NB), 128>>>(q, k, v, lf, tmphi, tmplo);

    gemm_bf16x3_kernel<<<dim3(2, (NB * NP) / 128), 256>>>(tmphi, tmplo, woh, wol, bo, out);
}

// round 10
// speedup vs baseline: 1.4641x; 1.1418x over previous
#include <cuda_runtime.h>
#include <cuda_fp16.h>
#include <cuda_bf16.h>
#include <stdint.h>
#include <stddef.h>
#include <math.h>

#define NB   4
#define NP   1024
#define DD   256
#define HWT  4096
#define HEADS 8
#define DH   32

#define LF_ELEMS  ((size_t)NB*NP*DD)   // 1M
#define GF_ELEMS  ((size_t)NB*HWT*DD)  // 4M
__device__ float g_scratch[17 * 1024 * 1024];

#define LN10K 9.210340371976184f

// ---------------------------------------------------------------------------
// helpers
// ---------------------------------------------------------------------------
__device__ __forceinline__ void cp16(uint32_t dst, const void* src) {
    asm volatile("cp.async.cg.shared.global [%0], [%1], 16;\n" :: "r"(dst), "l"(src));
}
__device__ __forceinline__ uint32_t smem_u32(const void* p) {
    return (uint32_t)__cvta_generic_to_shared(p);
}
__device__ __forceinline__ void mma_bf16(float& c0, float& c1, float& c2, float& c3,
                                         const uint32_t a[4], uint32_t b0, uint32_t b1) {
    asm volatile(
        "mma.sync.aligned.m16n8k16.row.col.f32.bf16.bf16.f32 "
        "{%0,%1,%2,%3}, {%4,%5,%6,%7}, {%8,%9}, {%0,%1,%2,%3};\n"
        : "+f"(c0), "+f"(c1), "+f"(c2), "+f"(c3)
        : "r"(a[0]), "r"(a[1]), "r"(a[2]), "r"(a[3]), "r"(b0), "r"(b1));
}
__device__ __forceinline__ void mma_f16(float& c0, float& c1, float& c2, float& c3,
                                        uint32_t a0, uint32_t a1, uint32_t a2, uint32_t a3,
                                        uint32_t b0, uint32_t b1) {
    asm volatile(
        "mma.sync.aligned.m16n8k16.row.col.f32.f16.f16.f32 "
        "{%0,%1,%2,%3}, {%4,%5,%6,%7}, {%8,%9}, {%0,%1,%2,%3};\n"
        : "+f"(c0), "+f"(c1), "+f"(c2), "+f"(c3)
        : "r"(a0), "r"(a1), "r"(a2), "r"(a3), "r"(b0), "r"(b1));
}
__device__ __forceinline__ void ldsm_x4_trans(uint32_t& r0, uint32_t& r1,
                                              uint32_t& r2, uint32_t& r3, uint32_t addr) {
    asm volatile("ldmatrix.sync.aligned.m8n8.x4.trans.shared.b16 {%0,%1,%2,%3}, [%4];\n"
                 : "=r"(r0), "=r"(r1), "=r"(r2), "=r"(r3) : "r"(addr));
}
__device__ __forceinline__ uint32_t pack_h2(float lo, float hi) {
    __half2 h = __floats2half2_rn(lo, hi);
    return *reinterpret_cast<uint32_t*>(&h);
}
__device__ __forceinline__ void split_pack_bf2(float a, float b, uint32_t& hi, uint32_t& lo) {
    __nv_bfloat16 ah = __float2bfloat16_rn(a);
    __nv_bfloat16 bh = __float2bfloat16_rn(b);
    float ar = a - __bfloat162float(ah);
    float br = b - __bfloat162float(bh);
    __nv_bfloat162 h2 = __halves2bfloat162(ah, bh);
    __nv_bfloat162 l2 = __floats2bfloat162_rn(ar, br);
    hi = *reinterpret_cast<uint32_t*>(&h2);
    lo = *reinterpret_cast<uint32_t*>(&l2);
}

// ---------------------------------------------------------------------------
// PE local: lf = local_feat + PE (fp32) AND packed bf16 hi/lo
// ---------------------------------------------------------------------------
__global__ void pe_local_kernel(const float* __restrict__ in, float* __restrict__ lf,
                                uint32_t* __restrict__ lfhi, uint32_t* __restrict__ lflo) {
    int idx = blockIdx.x * blockDim.x + threadIdx.x;
    if (idx >= (int)(LF_ELEMS / 2)) return;
    int d2 = idx & 127;
    int p  = (idx >> 7) & (NP - 1);
    int d  = 2 * d2;
    float div = expf((float)d * (-LN10K / 256.0f));
    float x = (float)(p & 31) * (1.0f / 31.0f);
    float y = (float)(p >> 5) * (1.0f / 31.0f);
    float2 v = *(const float2*)(in + (size_t)idx * 2);
    float v0 = v.x + sinf(x * div);
    float v1 = v.y + cosf(y * div);
    *(float2*)(lf + (size_t)idx * 2) = make_float2(v0, v1);
    uint32_t hi, lo;
    split_pack_bf2(v0, v1, hi, lo);
    lfhi[idx] = hi;
    lflo[idx] = lo;
}

// ---------------------------------------------------------------------------
// PE global: transpose (NB,DD,HWT) -> packed bf16 hi/lo (NB,HWT,128 u32)
// ---------------------------------------------------------------------------
__global__ __launch_bounds__(256) void pe_global_kernel(const float* __restrict__ in,
                                                        uint32_t* __restrict__ gfhi,
                                                        uint32_t* __restrict__ gflo) {
    __shared__ float tile[32][33];
    const int tid = threadIdx.x;
    const int tx = tid & 31;
    const int ty = tid >> 5;
    const int t0 = blockIdx.x << 5;
    const int d0 = blockIdx.y << 5;
    const int b  = blockIdx.z;

    #pragma unroll
    for (int i = 0; i < 4; i++) {
        int d = d0 + ty + i * 8;
        tile[ty + i * 8][tx] = in[((size_t)b * DD + d) * HWT + t0 + tx];
    }
    __syncthreads();

    const int dp = tid & 15;
    #pragma unroll
    for (int i = 0; i < 2; i++) {
        int tr = (tid >> 4) + i * 16;
        int t = t0 + tr;
        int d = d0 + 2 * dp;
        float div = expf((float)d * (-LN10K / 256.0f));
        float x = (float)(t & 63) * (1.0f / 63.0f);
        float y = (float)(t >> 6) * (1.0f / 63.0f);
        float v0 = tile[2 * dp][tr]     + sinf(x * div);
        float v1 = tile[2 * dp + 1][tr] + cosf(y * div);
        uint32_t hi, lo;
        split_pack_bf2(v0, v1, hi, lo);
        size_t o = ((size_t)b * HWT + t) * 128 + d0 / 2 + dp;
        gfhi[o] = hi;
        gflo[o] = lo;
    }
}

// ---------------------------------------------------------------------------
// Split weights into packed bf16 hi/lo; Wk,Wv stacked into wkv; bias bk||bv.
// ---------------------------------------------------------------------------
__global__ void split_w_kernel(const float* __restrict__ Wq, const float* __restrict__ Wk,
                               const float* __restrict__ Wv, const float* __restrict__ Wo,
                               const float* __restrict__ bk, const float* __restrict__ bv,
                               uint32_t* __restrict__ wqh, uint32_t* __restrict__ wql,
                               uint32_t* __restrict__ wkvh, uint32_t* __restrict__ wkvl,
                               uint32_t* __restrict__ woh, uint32_t* __restrict__ wol,
                               float* __restrict__ bkv) {
    int idx = blockIdx.x * blockDim.x + threadIdx.x;   // pair 0..32767
    int m = blockIdx.y;
    const float* W; uint32_t *oh, *ol; size_t off = idx;
    if (m == 0)      { W = Wq; oh = wqh;          ol = wql;          }
    else if (m == 1) { W = Wk; oh = wkvh;         ol = wkvl;         }
    else if (m == 2) { W = Wv; oh = wkvh + 32768; ol = wkvl + 32768; }
    else             { W = Wo; oh = woh;          ol = wol;          }
    float2 v = *(const float2*)(W + (size_t)idx * 2);
    uint32_t hi, lo;
    split_pack_bf2(v.x, v.y, hi, lo);
    oh[off] = hi;
    ol[off] = lo;
    if (m == 0 && idx < 512)
        bkv[idx] = (idx < 256) ? bk[idx] : bv[idx - 256];
}

// ---------------------------------------------------------------------------
// bf16x3 GEMM. OUTHALF=1: writes packed __half2 with per-tile scale, row
// stride ldc; OUTHALF=0: fp32, ldc=256.
// ---------------------------------------------------------------------------
template<int OUTHALF>
__global__ __launch_bounds__(256) void gemm_bf16x3_kernel(
    const uint32_t* __restrict__ Ahi, const uint32_t* __restrict__ Alo,
    const uint32_t* __restrict__ Whi, const uint32_t* __restrict__ Wlo,
    const float* __restrict__ bias, void* __restrict__ Cout,
    float kscale, int ldc)
{
    __shared__ uint32_t sAh[2][128][12];
    __shared__ uint32_t sAl[2][128][12];
    __shared__ uint32_t sWh[2][128][12];
    __shared__ uint32_t sWl[2][128][12];

    const int tid  = threadIdx.x;
    const int warp = tid >> 5;
    const int lane = tid & 31;
    const int gi = lane >> 2;
    const int ci = lane & 3;
    const int mBase = blockIdx.y << 7;
    const int nBase = blockIdx.x << 7;
    const int wm = (warp & 3) << 5;
    const int wn = (warp >> 2) << 6;

    const int arr = tid >> 6;
    const int r0 = (tid & 63) * 2;
    const uint32_t* gsrc = (arr == 0) ? Ahi + (size_t)mBase * 128
                         : (arr == 1) ? Alo + (size_t)mBase * 128
                         : (arr == 2) ? Whi + (size_t)nBase * 128
                                      : Wlo + (size_t)nBase * 128;
    uint32_t sdst = (arr == 0) ? smem_u32(&sAh[0][0][0])
                  : (arr == 1) ? smem_u32(&sAl[0][0][0])
                  : (arr == 2) ? smem_u32(&sWh[0][0][0])
                               : smem_u32(&sWl[0][0][0]);
    const uint32_t stageBytes = 128 * 12 * 4;

    float acc[2][8][4];
    #pragma unroll
    for (int mt = 0; mt < 2; mt++)
        #pragma unroll
        for (int nt = 0; nt < 8; nt++)
            #pragma unroll
            for (int i = 0; i < 4; i++) acc[mt][nt][i] = 0.0f;

    #pragma unroll
    for (int j = 0; j < 4; j++) {
        int row = r0 + (j >> 1), half = j & 1;
        cp16(sdst + (row * 12 + half * 4) * 4, gsrc + (size_t)row * 128 + half * 4);
    }
    asm volatile("cp.async.commit_group;\n");

    for (int kt = 0; kt < 16; kt++) {
        const int buf = kt & 1;
        if (kt < 15) {
            const int k0u = (kt + 1) * 8;
            uint32_t d2 = sdst + (buf ^ 1) * stageBytes;
            #pragma unroll
            for (int j = 0; j < 4; j++) {
                int row = r0 + (j >> 1), half = j & 1;
                cp16(d2 + (row * 12 + half * 4) * 4, gsrc + (size_t)row * 128 + k0u + half * 4);
            }
            asm volatile("cp.async.commit_group;\n");
            asm volatile("cp.async.wait_group 1;\n");
        } else {
            asm volatile("cp.async.wait_group 0;\n");
        }
        __syncthreads();

        uint32_t ah[2][4], al[2][4];
        #pragma unroll
        for (int mt = 0; mt < 2; mt++) {
            int rA = wm + mt * 16 + gi;
            ah[mt][0] = sAh[buf][rA    ][ci    ];
            ah[mt][1] = sAh[buf][rA + 8][ci    ];
            ah[mt][2] = sAh[buf][rA    ][ci + 4];
            ah[mt][3] = sAh[buf][rA + 8][ci + 4];
            al[mt][0] = sAl[buf][rA    ][ci    ];
            al[mt][1] = sAl[buf][rA + 8][ci    ];
            al[mt][2] = sAl[buf][rA    ][ci + 4];
            al[mt][3] = sAl[buf][rA + 8][ci + 4];
        }
        #pragma unroll
        for (int nt = 0; nt < 8; nt++) {
            int rW = wn + nt * 8 + gi;
            uint32_t bh0 = sWh[buf][rW][ci    ];
            uint32_t bh1 = sWh[buf][rW][ci + 4];
            uint32_t bl0 = sWl[buf][rW][ci    ];
            uint32_t bl1 = sWl[buf][rW][ci + 4];
            #pragma unroll
            for (int mt = 0; mt < 2; mt++) {
                mma_bf16(acc[mt][nt][0], acc[mt][nt][1], acc[mt][nt][2], acc[mt][nt][3],
                         al[mt], bh0, bh1);
                mma_bf16(acc[mt][nt][0], acc[mt][nt][1], acc[mt][nt][2], acc[mt][nt][3],
                         ah[mt], bl0, bl1);
                mma_bf16(acc[mt][nt][0], acc[mt][nt][1], acc[mt][nt][2], acc[mt][nt][3],
                         ah[mt], bh0, bh1);
            }
        }
        __syncthreads();
    }

    const float sc = OUTHALF ? ((nBase < 256) ? kscale : 1.0f) : 1.0f;
    #pragma unroll
    for (int mt = 0; mt < 2; mt++) {
        #pragma unroll
        for (int nt = 0; nt < 8; nt++) {
            int ncol = nBase + wn + nt * 8 + 2 * ci;
            float2 bs = *(const float2*)(bias + ncol);
            int row = mBase + wm + mt * 16 + gi;
            float c00 = (acc[mt][nt][0] + bs.x) * sc;
            float c01 = (acc[mt][nt][1] + bs.y) * sc;
            float c10 = (acc[mt][nt][2] + bs.x) * sc;
            float c11 = (acc[mt][nt][3] + bs.y) * sc;
            if (OUTHALF) {
                uint32_t* C = (uint32_t*)Cout;
                C[(size_t)row * (ldc / 2) + ncol / 2]       = pack_h2(c00, c01);
                C[(size_t)(row + 8) * (ldc / 2) + ncol / 2] = pack_h2(c10, c11);
            } else {
                float* C = (float*)Cout;
                *(float2*)(C + (size_t)row * 256 + ncol)       = make_float2(c00, c01);
                *(float2*)(C + (size_t)(row + 8) * 256 + ncol) = make_float2(c10, c11);
            }
        }
    }
}

// ---------------------------------------------------------------------------
// Flash attention on half inputs. q[token][256] half (unscaled; K pre-scaled),
// kv[token][512] half (K cols 0-255 scaled, V cols 256-511).
// 128 queries/block, KV tile 64, double buffered, one barrier/tile.
// ---------------------------------------------------------------------------
__global__ __launch_bounds__(128, 4) void flash_mma_kernel(
    const __half* __restrict__ q, const __half* __restrict__ kv,
    const float* __restrict__ lf,
    uint32_t* __restrict__ tmphi, uint32_t* __restrict__ tmplo)
{
    __shared__ uint32_t Kh[2][64][20];   // [key][dh/2] u32 (pad 16->20)
    __shared__ __half   Vsh[2][64][40];  // [key][dh] half (pad 32->40)

    const int tid  = threadIdx.x;
    const int warp = tid >> 5;
    const int lane = tid & 31;
    const int gi = lane >> 2;
    const int ci = lane & 3;
    const int b = blockIdx.z;
    const int h = blockIdx.y;
    const int qbase = (blockIdx.x << 7) + warp * 32;

    // Q fragments: direct u32 loads from half q
    uint32_t qh[2][2][4];
    {
        const __half* qp = q + ((size_t)(b * NP + qbase)) * DD + h * DH;
        #pragma unroll
        for (int mt = 0; mt < 2; mt++)
            #pragma unroll
            for (int s = 0; s < 2; s++)
                #pragma unroll
                for (int r = 0; r < 4; r++) {
                    int row = mt * 16 + gi + (r & 1) * 8;
                    int col = s * 16 + 2 * ci + (r >> 1) * 8;
                    qh[mt][s][r] = *(const uint32_t*)(qp + (size_t)row * DD + col);
                }
    }

    float O[2][4][4];
    #pragma unroll
    for (int mt = 0; mt < 2; mt++)
        #pragma unroll
        for (int n = 0; n < 4; n++)
            #pragma unroll
            for (int i = 0; i < 4; i++) O[mt][n][i] = 0.0f;
    float mM[2][2], lS[2][2];
    #pragma unroll
    for (int mt = 0; mt < 2; mt++) {
        mM[mt][0] = -1e30f; mM[mt][1] = -1e30f;
        lS[mt][0] = 0.0f;   lS[mt][1] = 0.0f;
    }

    const __half* kbase = kv + (size_t)b * HWT * 512 + h * DH;         // K cols
    const __half* vbase = kv + (size_t)b * HWT * 512 + 256 + h * DH;   // V cols

    // prologue: tile 0 (2 K-chunks + 2 V-chunks of 16B per thread)
    #pragma unroll
    for (int j = 0; j < 2; j++) {
        int idx = tid * 2 + j;          // 0..255
        int key = idx >> 2, ch = idx & 3;
        cp16(smem_u32(&Kh[0][key][ch * 4]),  kbase + (size_t)key * 512 + ch * 8);
        cp16(smem_u32(&Vsh[0][key][ch * 8]), vbase + (size_t)key * 512 + ch * 8);
    }
    asm volatile("cp.async.commit_group;\n");

    for (int t = 0; t < 64; t++) {
        const int buf = t & 1;
        asm volatile("cp.async.wait_group 0;\n");
        __syncthreads();   // tile t visible to all; all reads of buf^1 finished
        if (t < 63) {
            const size_t kv0 = (size_t)(t + 1) << 6;
            #pragma unroll
            for (int j = 0; j < 2; j++) {
                int idx = tid * 2 + j;
                int key = idx >> 2, ch = idx & 3;
                cp16(smem_u32(&Kh[buf ^ 1][key][ch * 4]),
                     kbase + (kv0 + key) * 512 + ch * 8);
                cp16(smem_u32(&Vsh[buf ^ 1][key][ch * 8]),
                     vbase + (kv0 + key) * 512 + ch * 8);
            }
            asm volatile("cp.async.commit_group;\n");
        }

        #pragma unroll
        for (int mt = 0; mt < 2; mt++) {
            // ---- S = Q K^T ----
            float Sf[8][4];
            #pragma unroll
            for (int nt = 0; nt < 8; nt++) {
                float c0 = 0.f, c1 = 0.f, c2 = 0.f, c3 = 0.f;
                #pragma unroll
                for (int s = 0; s < 2; s++) {
                    uint32_t b0 = Kh[buf][nt * 8 + gi][s * 8 + ci];
                    uint32_t b1 = Kh[buf][nt * 8 + gi][s * 8 + ci + 4];
                    mma_f16(c0, c1, c2, c3,
                            qh[mt][s][0], qh[mt][s][1], qh[mt][s][2], qh[mt][s][3],
                            b0, b1);
                }
                Sf[nt][0] = c0; Sf[nt][1] = c1; Sf[nt][2] = c2; Sf[nt][3] = c3;
            }

            // ---- online softmax ----
            float mx0 = -1e30f, mx1 = -1e30f;
            #pragma unroll
            for (int nt = 0; nt < 8; nt++) {
                mx0 = fmaxf(mx0, fmaxf(Sf[nt][0], Sf[nt][1]));
                mx1 = fmaxf(mx1, fmaxf(Sf[nt][2], Sf[nt][3]));
            }
            mx0 = fmaxf(mx0, __shfl_xor_sync(0xffffffffu, mx0, 1));
            mx0 = fmaxf(mx0, __shfl_xor_sync(0xffffffffu, mx0, 2));
            mx1 = fmaxf(mx1, __shfl_xor_sync(0xffffffffu, mx1, 1));
            mx1 = fmaxf(mx1, __shfl_xor_sync(0xffffffffu, mx1, 2));

            float mn0 = fmaxf(mM[mt][0], mx0), mn1 = fmaxf(mM[mt][1], mx1);
            float corr0 = __expf(mM[mt][0] - mn0), corr1 = __expf(mM[mt][1] - mn1);
            float sum0 = 0.f, sum1 = 0.f;
            #pragma unroll
            for (int nt = 0; nt < 8; nt++) {
                Sf[nt][0] = __expf(Sf[nt][0] - mn0); sum0 += Sf[nt][0];
                Sf[nt][1] = __expf(Sf[nt][1] - mn0); sum0 += Sf[nt][1];
                Sf[nt][2] = __expf(Sf[nt][2] - mn1); sum1 += Sf[nt][2];
                Sf[nt][3] = __expf(Sf[nt][3] - mn1); sum1 += Sf[nt][3];
            }
            sum0 += __shfl_xor_sync(0xffffffffu, sum0, 1);
            sum0 += __shfl_xor_sync(0xffffffffu, sum0, 2);
            sum1 += __shfl_xor_sync(0xffffffffu, sum1, 1);
            sum1 += __shfl_xor_sync(0xffffffffu, sum1, 2);
            lS[mt][0] = lS[mt][0] * corr0 + sum0;
            lS[mt][1] = lS[mt][1] * corr1 + sum1;
            mM[mt][0] = mn0; mM[mt][1] = mn1;

            #pragma unroll
            for (int n = 0; n < 4; n++) {
                O[mt][n][0] *= corr0; O[mt][n][1] *= corr0;
                O[mt][n][2] *= corr1; O[mt][n][3] *= corr1;
            }

            // ---- O += P V ; B-fragments via ldmatrix.trans ----
            #pragma unroll
            for (int s = 0; s < 4; s++) {
                uint32_t a0 = pack_h2(Sf[2 * s][0],     Sf[2 * s][1]);
                uint32_t a1 = pack_h2(Sf[2 * s][2],     Sf[2 * s][3]);
                uint32_t a2 = pack_h2(Sf[2 * s + 1][0], Sf[2 * s + 1][1]);
                uint32_t a3 = pack_h2(Sf[2 * s + 1][2], Sf[2 * s + 1][3]);
                int mi = lane >> 3;                 // 0..3
                int key = s * 16 + (mi & 1) * 8 + (lane & 7);
                #pragma unroll
                for (int db = 0; db < 2; db++) {    // dh 0-15, 16-31
                    int dh0 = db * 16 + (mi >> 1) * 8;
                    uint32_t B0, B1, B2, B3;
                    ldsm_x4_trans(B0, B1, B2, B3, smem_u32(&Vsh[buf][key][dh0]));
                    mma_f16(O[mt][2 * db][0],     O[mt][2 * db][1],
                            O[mt][2 * db][2],     O[mt][2 * db][3],
                            a0, a1, a2, a3, B0, B1);
                    mma_f16(O[mt][2 * db + 1][0], O[mt][2 * db + 1][1],
                            O[mt][2 * db + 1][2], O[mt][2 * db + 1][3],
                            a0, a1, a2, a3, B2, B3);
                }
            }
        }
    }

    // Epilogue: out = O/l + lf, packed bf16 hi/lo for the O-projection GEMM
    const float* lfp = lf + ((size_t)(b * NP + qbase)) * DD + h * DH;
    uint32_t* th = tmphi + ((size_t)(b * NP + qbase)) * 128 + h * (DH / 2);
    uint32_t* tl = tmplo + ((size_t)(b * NP + qbase)) * 128 + h * (DH / 2);
    #pragma unroll
    for (int mt = 0; mt < 2; mt++) {
        float inv0 = 1.0f / lS[mt][0], inv1 = 1.0f / lS[mt][1];
        #pragma unroll
        for (int n = 0; n < 4; n++) {
            int row0 = mt * 16 + gi, row1 = row0 + 8;
            int col = n * 8 + 2 * ci;
            float2 L0 = *(const float2*)(lfp + (size_t)row0 * DD + col);
            float2 L1 = *(const float2*)(lfp + (size_t)row1 * DD + col);
            float a0 = O[mt][n][0] * inv0 + L0.x;
            float a1 = O[mt][n][1] * inv0 + L0.y;
            float b0 = O[mt][n][2] * inv1 + L1.x;
            float b1 = O[mt][n][3] * inv1 + L1.y;
            uint32_t hi, lo;
            split_pack_bf2(a0, a1, hi, lo);
            th[(size_t)row0 * 128 + col / 2] = hi;
            tl[(size_t)row0 * 128 + col / 2] = lo;
            split_pack_bf2(b0, b1, hi, lo);
            th[(size_t)row1 * 128 + col / 2] = hi;
            tl[(size_t)row1 * 128 + col / 2] = lo;
        }
    }
}

// ---------------------------------------------------------------------------
extern "C" void kernel_launch(void* const* d_in, const int* in_sizes, int n_in,
                              void* d_out, int out_size) {
    const float* local_feat  = (const float*)d_in[0];
    const float* global_feat = (const float*)d_in[1];
    const float* Wq = (const float*)d_in[2];
    const float* bq = (const float*)d_in[3];
    const float* Wk = (const float*)d_in[4];
    const float* bk = (const float*)d_in[5];
    const float* Wv = (const float*)d_in[6];
    const float* bv = (const float*)d_in[7];
    const float* Wo = (const float*)d_in[8];
    const float* bo = (const float*)d_in[9];
    float* out = (float*)d_out;

    float* base = nullptr;
    cudaGetSymbolAddress((void**)&base, g_scratch);
    float* lf = base;                                  // 1M fl
    __half* q  = (__half*)(lf + LF_ELEMS);             // 1M half = 0.5M fl
    __half* kv = q + LF_ELEMS;                         // 8M half = 4M fl
    uint32_t* lfhi  = (uint32_t*)(kv + 8 * 1024 * 1024);
    uint32_t* lflo  = lfhi  + LF_ELEMS / 2;
    uint32_t* gfhi  = lflo  + LF_ELEMS / 2;
    uint32_t* gflo  = gfhi  + GF_ELEMS / 2;
    uint32_t* tmphi = gflo  + GF_ELEMS / 2;
    uint32_t* tmplo = tmphi + LF_ELEMS / 2;
    uint32_t* wqh   = tmplo + LF_ELEMS / 2;            // 32768 each
    uint32_t* wql   = wqh + 32768;
    uint32_t* wkvh  = wql + 32768;                     // 65536 each
    uint32_t* wkvl  = wkvh + 65536;
    uint32_t* woh   = wkvl + 65536;
    uint32_t* wol   = woh + 32768;
    float*    bkv   = (float*)(wol + 32768);           // 512

    split_w_kernel<<<dim3(128, 4), 256>>>(Wq, Wk, Wv, Wo, bk, bv,
                                          wqh, wql, wkvh, wkvl, woh, wol, bkv);
    pe_local_kernel<<<(int)(LF_ELEMS / 2 / 256), 256>>>(local_feat, lf, lfhi, lflo);
    pe_global_kernel<<<dim3(HWT / 32, DD / 32, NB), 256>>>(global_feat, gfhi, gflo);

    const float kscale = 0.17677669529663687f;  // 1/sqrt(32)
    gemm_bf16x3_kernel<1><<<dim3(2, (NB * NP)  / 128), 256>>>(lfhi, lflo, wqh, wql, bq,
                                                              q, 1.0f, 256);
    gemm_bf16x3_kernel<1><<<dim3(4, (NB * HWT) / 128), 256>>>(gfhi, gflo, wkvh, wkvl, bkv,
                                                              kv, kscale, 512);

    flash_mma_kernel<<<dim3(NP / 128, HEADS, NB), 128>>>(q, kv, lf, tmphi, tmplo);

    gemm_bf16x3_kernel<0><<<dim3(2, (NB * NP) / 128), 256>>>(tmphi, tmplo, woh, wol, bo,
                                                             out, 1.0f, 256);
}

// round 11
// speedup vs baseline: 1.5687x; 1.0714x over previous
#include <cuda_runtime.h>
#include <cuda_fp16.h>
#include <cuda_bf16.h>
#include <stdint.h>
#include <stddef.h>
#include <math.h>

#define NB   4
#define NP   1024
#define DD   256
#define HWT  4096
#define HEADS 8
#define DH   32

#define LF_ELEMS  ((size_t)NB*NP*DD)   // 1M
#define GF_ELEMS  ((size_t)NB*HWT*DD)  // 4M
__device__ float g_scratch[17 * 1024 * 1024];

#define LN10K 9.210340371976184f
// 1/sqrt(32) * log2(e): K prescale so scores are in exp2 domain
#define KSCALE_EX2 0.25503482f

// ---------------------------------------------------------------------------
// helpers
// ---------------------------------------------------------------------------
__device__ __forceinline__ void cp16(uint32_t dst, const void* src) {
    asm volatile("cp.async.cg.shared.global [%0], [%1], 16;\n" :: "r"(dst), "l"(src));
}
__device__ __forceinline__ uint32_t smem_u32(const void* p) {
    return (uint32_t)__cvta_generic_to_shared(p);
}
__device__ __forceinline__ void mma_bf16(float& c0, float& c1, float& c2, float& c3,
                                         const uint32_t a[4], uint32_t b0, uint32_t b1) {
    asm volatile(
        "mma.sync.aligned.m16n8k16.row.col.f32.bf16.bf16.f32 "
        "{%0,%1,%2,%3}, {%4,%5,%6,%7}, {%8,%9}, {%0,%1,%2,%3};\n"
        : "+f"(c0), "+f"(c1), "+f"(c2), "+f"(c3)
        : "r"(a[0]), "r"(a[1]), "r"(a[2]), "r"(a[3]), "r"(b0), "r"(b1));
}
__device__ __forceinline__ void mma_f16(float& c0, float& c1, float& c2, float& c3,
                                        uint32_t a0, uint32_t a1, uint32_t a2, uint32_t a3,
                                        uint32_t b0, uint32_t b1) {
    asm volatile(
        "mma.sync.aligned.m16n8k16.row.col.f32.f16.f16.f32 "
        "{%0,%1,%2,%3}, {%4,%5,%6,%7}, {%8,%9}, {%0,%1,%2,%3};\n"
        : "+f"(c0), "+f"(c1), "+f"(c2), "+f"(c3)
        : "r"(a0), "r"(a1), "r"(a2), "r"(a3), "r"(b0), "r"(b1));
}
__device__ __forceinline__ void ldsm_x4_trans(uint32_t& r0, uint32_t& r1,
                                              uint32_t& r2, uint32_t& r3, uint32_t addr) {
    asm volatile("ldmatrix.sync.aligned.m8n8.x4.trans.shared.b16 {%0,%1,%2,%3}, [%4];\n"
                 : "=r"(r0), "=r"(r1), "=r"(r2), "=r"(r3) : "r"(addr));
}
__device__ __forceinline__ float ex2(float x) {
    float r;
    asm("ex2.approx.f32 %0, %1;" : "=f"(r) : "f"(x));
    return r;
}
__device__ __forceinline__ uint32_t pack_h2(float lo, float hi) {
    __half2 h = __floats2half2_rn(lo, hi);
    return *reinterpret_cast<uint32_t*>(&h);
}
__device__ __forceinline__ void split_pack_bf2(float a, float b, uint32_t& hi, uint32_t& lo) {
    __nv_bfloat16 ah = __float2bfloat16_rn(a);
    __nv_bfloat16 bh = __float2bfloat16_rn(b);
    float ar = a - __bfloat162float(ah);
    float br = b - __bfloat162float(bh);
    __nv_bfloat162 h2 = __halves2bfloat162(ah, bh);
    __nv_bfloat162 l2 = __floats2bfloat162_rn(ar, br);
    hi = *reinterpret_cast<uint32_t*>(&h2);
    lo = *reinterpret_cast<uint32_t*>(&l2);
}

// ---------------------------------------------------------------------------
// PE local
// ---------------------------------------------------------------------------
__global__ void pe_local_kernel(const float* __restrict__ in, float* __restrict__ lf,
                                uint32_t* __restrict__ lfhi, uint32_t* __restrict__ lflo) {
    int idx = blockIdx.x * blockDim.x + threadIdx.x;
    if (idx >= (int)(LF_ELEMS / 2)) return;
    int d2 = idx & 127;
    int p  = (idx >> 7) & (NP - 1);
    int d  = 2 * d2;
    float div = expf((float)d * (-LN10K / 256.0f));
    float x = (float)(p & 31) * (1.0f / 31.0f);
    float y = (float)(p >> 5) * (1.0f / 31.0f);
    float2 v = *(const float2*)(in + (size_t)idx * 2);
    float v0 = v.x + sinf(x * div);
    float v1 = v.y + cosf(y * div);
    *(float2*)(lf + (size_t)idx * 2) = make_float2(v0, v1);
    uint32_t hi, lo;
    split_pack_bf2(v0, v1, hi, lo);
    lfhi[idx] = hi;
    lflo[idx] = lo;
}

// ---------------------------------------------------------------------------
// PE global: transpose + PE -> packed bf16 hi/lo
// ---------------------------------------------------------------------------
__global__ __launch_bounds__(256) void pe_global_kernel(const float* __restrict__ in,
                                                        uint32_t* __restrict__ gfhi,
                                                        uint32_t* __restrict__ gflo) {
    __shared__ float tile[32][33];
    const int tid = threadIdx.x;
    const int tx = tid & 31;
    const int ty = tid >> 5;
    const int t0 = blockIdx.x << 5;
    const int d0 = blockIdx.y << 5;
    const int b  = blockIdx.z;

    #pragma unroll
    for (int i = 0; i < 4; i++) {
        int d = d0 + ty + i * 8;
        tile[ty + i * 8][tx] = in[((size_t)b * DD + d) * HWT + t0 + tx];
    }
    __syncthreads();

    const int dp = tid & 15;
    #pragma unroll
    for (int i = 0; i < 2; i++) {
        int tr = (tid >> 4) + i * 16;
        int t = t0 + tr;
        int d = d0 + 2 * dp;
        float div = expf((float)d * (-LN10K / 256.0f));
        float x = (float)(t & 63) * (1.0f / 63.0f);
        float y = (float)(t >> 6) * (1.0f / 63.0f);
        float v0 = tile[2 * dp][tr]     + sinf(x * div);
        float v1 = tile[2 * dp + 1][tr] + cosf(y * div);
        uint32_t hi, lo;
        split_pack_bf2(v0, v1, hi, lo);
        size_t o = ((size_t)b * HWT + t) * 128 + d0 / 2 + dp;
        gfhi[o] = hi;
        gflo[o] = lo;
    }
}

// ---------------------------------------------------------------------------
// Split weights (Wk,Wv stacked); bias bk||bv
// ---------------------------------------------------------------------------
__global__ void split_w_kernel(const float* __restrict__ Wq, const float* __restrict__ Wk,
                               const float* __restrict__ Wv, const float* __restrict__ Wo,
                               const float* __restrict__ bk, const float* __restrict__ bv,
                               uint32_t* __restrict__ wqh, uint32_t* __restrict__ wql,
                               uint32_t* __restrict__ wkvh, uint32_t* __restrict__ wkvl,
                               uint32_t* __restrict__ woh, uint32_t* __restrict__ wol,
                               float* __restrict__ bkv) {
    int idx = blockIdx.x * blockDim.x + threadIdx.x;
    int m = blockIdx.y;
    const float* W; uint32_t *oh, *ol;
    if (m == 0)      { W = Wq; oh = wqh;          ol = wql;          }
    else if (m == 1) { W = Wk; oh = wkvh;         ol = wkvl;         }
    else if (m == 2) { W = Wv; oh = wkvh + 32768; ol = wkvl + 32768; }
    else             { W = Wo; oh = woh;          ol = wol;          }
    float2 v = *(const float2*)(W + (size_t)idx * 2);
    uint32_t hi, lo;
    split_pack_bf2(v.x, v.y, hi, lo);
    oh[idx] = hi;
    ol[idx] = lo;
    if (m == 0 && idx < 512)
        bkv[idx] = (idx < 256) ? bk[idx] : bv[idx - 256];
}

// ---------------------------------------------------------------------------
// bf16x3 GEMM body, shared by the merged QKV kernel and the O kernel.
// Computes a 128x128 tile of C = A@W^T + bias, output half (scaled) or fp32.
// ---------------------------------------------------------------------------
struct GemmArgs {
    const uint32_t *Ahi, *Alo, *Whi, *Wlo;
    const float* bias;
    void* Cout;
    int mBase, nBase, ldc;
    float scale;
    int outhalf;
};

__device__ __forceinline__ void gemm_tile_body(const GemmArgs& ga) {
    __shared__ uint32_t sAh[2][128][12];
    __shared__ uint32_t sAl[2][128][12];
    __shared__ uint32_t sWh[2][128][12];
    __shared__ uint32_t sWl[2][128][12];

    const int tid  = threadIdx.x;
    const int warp = tid >> 5;
    const int lane = tid & 31;
    const int gi = lane >> 2;
    const int ci = lane & 3;
    const int wm = (warp & 3) << 5;
    const int wn = (warp >> 2) << 6;

    const int arr = tid >> 6;
    const int r0 = (tid & 63) * 2;
    const uint32_t* gsrc = (arr == 0) ? ga.Ahi + (size_t)ga.mBase * 128
                         : (arr == 1) ? ga.Alo + (size_t)ga.mBase * 128
                         : (arr == 2) ? ga.Whi + (size_t)ga.nBase * 128
                                      : ga.Wlo + (size_t)ga.nBase * 128;
    uint32_t sdst = (arr == 0) ? smem_u32(&sAh[0][0][0])
                  : (arr == 1) ? smem_u32(&sAl[0][0][0])
                  : (arr == 2) ? smem_u32(&sWh[0][0][0])
                               : smem_u32(&sWl[0][0][0]);
    const uint32_t stageBytes = 128 * 12 * 4;

    float acc[2][8][4];
    #pragma unroll
    for (int mt = 0; mt < 2; mt++)
        #pragma unroll
        for (int nt = 0; nt < 8; nt++)
            #pragma unroll
            for (int i = 0; i < 4; i++) acc[mt][nt][i] = 0.0f;

    #pragma unroll
    for (int j = 0; j < 4; j++) {
        int row = r0 + (j >> 1), half = j & 1;
        cp16(sdst + (row * 12 + half * 4) * 4, gsrc + (size_t)row * 128 + half * 4);
    }
    asm volatile("cp.async.commit_group;\n");

    for (int kt = 0; kt < 16; kt++) {
        const int buf = kt & 1;
        if (kt < 15) {
            const int k0u = (kt + 1) * 8;
            uint32_t d2 = sdst + (buf ^ 1) * stageBytes;
            #pragma unroll
            for (int j = 0; j < 4; j++) {
                int row = r0 + (j >> 1), half = j & 1;
                cp16(d2 + (row * 12 + half * 4) * 4, gsrc + (size_t)row * 128 + k0u + half * 4);
            }
            asm volatile("cp.async.commit_group;\n");
            asm volatile("cp.async.wait_group 1;\n");
        } else {
            asm volatile("cp.async.wait_group 0;\n");
        }
        __syncthreads();

        uint32_t ah[2][4], al[2][4];
        #pragma unroll
        for (int mt = 0; mt < 2; mt++) {
            int rA = wm + mt * 16 + gi;
            ah[mt][0] = sAh[buf][rA    ][ci    ];
            ah[mt][1] = sAh[buf][rA + 8][ci    ];
            ah[mt][2] = sAh[buf][rA    ][ci + 4];
            ah[mt][3] = sAh[buf][rA + 8][ci + 4];
            al[mt][0] = sAl[buf][rA    ][ci    ];
            al[mt][1] = sAl[buf][rA + 8][ci    ];
            al[mt][2] = sAl[buf][rA    ][ci + 4];
            al[mt][3] = sAl[buf][rA + 8][ci + 4];
        }
        #pragma unroll
        for (int nt = 0; nt < 8; nt++) {
            int rW = wn + nt * 8 + gi;
            uint32_t bh0 = sWh[buf][rW][ci    ];
            uint32_t bh1 = sWh[buf][rW][ci + 4];
            uint32_t bl0 = sWl[buf][rW][ci    ];
            uint32_t bl1 = sWl[buf][rW][ci + 4];
            #pragma unroll
            for (int mt = 0; mt < 2; mt++) {
                mma_bf16(acc[mt][nt][0], acc[mt][nt][1], acc[mt][nt][2], acc[mt][nt][3],
                         al[mt], bh0, bh1);
                mma_bf16(acc[mt][nt][0], acc[mt][nt][1], acc[mt][nt][2], acc[mt][nt][3],
                         ah[mt], bl0, bl1);
                mma_bf16(acc[mt][nt][0], acc[mt][nt][1], acc[mt][nt][2], acc[mt][nt][3],
                         ah[mt], bh0, bh1);
            }
        }
        __syncthreads();
    }

    #pragma unroll
    for (int mt = 0; mt < 2; mt++) {
        #pragma unroll
        for (int nt = 0; nt < 8; nt++) {
            int ncol = ga.nBase + wn + nt * 8 + 2 * ci;
            float2 bs = *(const float2*)(ga.bias + ncol);
            int row = ga.mBase + wm + mt * 16 + gi;
            float c00 = (acc[mt][nt][0] + bs.x) * ga.scale;
            float c01 = (acc[mt][nt][1] + bs.y) * ga.scale;
            float c10 = (acc[mt][nt][2] + bs.x) * ga.scale;
            float c11 = (acc[mt][nt][3] + bs.y) * ga.scale;
            if (ga.outhalf) {
                uint32_t* C = (uint32_t*)ga.Cout;
                C[(size_t)row * (ga.ldc / 2) + ncol / 2]       = pack_h2(c00, c01);
                C[(size_t)(row + 8) * (ga.ldc / 2) + ncol / 2] = pack_h2(c10, c11);
            } else {
                float* C = (float*)ga.Cout;
                *(float2*)(C + (size_t)row * 256 + ncol)       = make_float2(c00, c01);
                *(float2*)(C + (size_t)(row + 8) * 256 + ncol) = make_float2(c10, c11);
            }
        }
    }
}

// Merged Q + KV projection: blocks [0,512) do KV, [512,576) do Q.
__global__ __launch_bounds__(256) void gemm_qkv_kernel(
    const uint32_t* __restrict__ lfhi, const uint32_t* __restrict__ lflo,
    const uint32_t* __restrict__ gfhi, const uint32_t* __restrict__ gflo,
    const uint32_t* __restrict__ wqh,  const uint32_t* __restrict__ wql,
    const uint32_t* __restrict__ wkvh, const uint32_t* __restrict__ wkvl,
    const float* __restrict__ bq, const float* __restrict__ bkv,
    __half* __restrict__ qout, __half* __restrict__ kvout)
{
    GemmArgs ga;
    ga.outhalf = 1;
    int bid = blockIdx.x;
    if (bid < 512) {                      // KV: N=512, M=16384
        int bx = bid & 3, by = bid >> 2;
        ga.Ahi = gfhi; ga.Alo = gflo;
        ga.Whi = wkvh; ga.Wlo = wkvl;
        ga.bias = bkv; ga.Cout = kvout;
        ga.mBase = by << 7; ga.nBase = bx << 7; ga.ldc = 512;
        ga.scale = (ga.nBase < 256) ? KSCALE_EX2 : 1.0f;   // K prescaled into exp2 domain
    } else {                              // Q: N=256, M=4096
        int q = bid - 512;
        int bx = q & 1, by = q >> 1;
        ga.Ahi = lfhi; ga.Alo = lflo;
        ga.Whi = wqh;  ga.Wlo = wql;
        ga.bias = bq;  ga.Cout = qout;
        ga.mBase = by << 7; ga.nBase = bx << 7; ga.ldc = 256;
        ga.scale = 1.0f;
    }
    gemm_tile_body(ga);
}

// O projection (fp32 out)
__global__ __launch_bounds__(256) void gemm_o_kernel(
    const uint32_t* __restrict__ Ahi, const uint32_t* __restrict__ Alo,
    const uint32_t* __restrict__ Whi, const uint32_t* __restrict__ Wlo,
    const float* __restrict__ bias, float* __restrict__ C)
{
    GemmArgs ga;
    ga.Ahi = Ahi; ga.Alo = Alo; ga.Whi = Whi; ga.Wlo = Wlo;
    ga.bias = bias; ga.Cout = C;
    ga.mBase = (int)blockIdx.y << 7; ga.nBase = (int)blockIdx.x << 7;
    ga.ldc = 256; ga.scale = 1.0f; ga.outhalf = 0;
    gemm_tile_body(ga);
}

// ---------------------------------------------------------------------------
// Flash attention: 256 queries/block (8 warps x 32), KV tile 64, double buffer.
// Scores arrive in exp2 domain (K prescaled by log2e/sqrt(dh)); ex2 softmax.
// ---------------------------------------------------------------------------
__global__ __launch_bounds__(256, 2) void flash_mma_kernel(
    const __half* __restrict__ q, const __half* __restrict__ kv,
    const float* __restrict__ lf,
    uint32_t* __restrict__ tmphi, uint32_t* __restrict__ tmplo)
{
    __shared__ uint32_t Kh[2][64][20];
    __shared__ __half   Vsh[2][64][40];

    const int tid  = threadIdx.x;
    const int warp = tid >> 5;
    const int lane = tid & 31;
    const int gi = lane >> 2;
    const int ci = lane & 3;
    const int b = blockIdx.z;
    const int h = blockIdx.y;
    const int qbase = (blockIdx.x << 8) + warp * 32;

    uint32_t qh[2][2][4];
    {
        const __half* qp = q + ((size_t)(b * NP + qbase)) * DD + h * DH;
        #pragma unroll
        for (int mt = 0; mt < 2; mt++)
            #pragma unroll
            for (int s = 0; s < 2; s++)
                #pragma unroll
                for (int r = 0; r < 4; r++) {
                    int row = mt * 16 + gi + (r & 1) * 8;
                    int col = s * 16 + 2 * ci + (r >> 1) * 8;
                    qh[mt][s][r] = *(const uint32_t*)(qp + (size_t)row * DD + col);
                }
    }

    float O[2][4][4];
    #pragma unroll
    for (int mt = 0; mt < 2; mt++)
        #pragma unroll
        for (int n = 0; n < 4; n++)
            #pragma unroll
            for (int i = 0; i < 4; i++) O[mt][n][i] = 0.0f;
    float mM[2][2], lS[2][2];
    #pragma unroll
    for (int mt = 0; mt < 2; mt++) {
        mM[mt][0] = -1e30f; mM[mt][1] = -1e30f;
        lS[mt][0] = 0.0f;   lS[mt][1] = 0.0f;
    }

    const __half* kbase = kv + (size_t)b * HWT * 512 + h * DH;
    const __half* vbase = kv + (size_t)b * HWT * 512 + 256 + h * DH;

    // prologue: 256 threads, 1 K-chunk + 1 V-chunk each
    {
        int key = tid >> 2, ch = tid & 3;
        cp16(smem_u32(&Kh[0][key][ch * 4]),  kbase + (size_t)key * 512 + ch * 8);
        cp16(smem_u32(&Vsh[0][key][ch * 8]), vbase + (size_t)key * 512 + ch * 8);
    }
    asm volatile("cp.async.commit_group;\n");

    for (int t = 0; t < 64; t++) {
        const int buf = t & 1;
        asm volatile("cp.async.wait_group 0;\n");
        __syncthreads();
        if (t < 63) {
            const size_t kv0 = (size_t)(t + 1) << 6;
            int key = tid >> 2, ch = tid & 3;
            cp16(smem_u32(&Kh[buf ^ 1][key][ch * 4]),
                 kbase + (kv0 + key) * 512 + ch * 8);
            cp16(smem_u32(&Vsh[buf ^ 1][key][ch * 8]),
                 vbase + (kv0 + key) * 512 + ch * 8);
            asm volatile("cp.async.commit_group;\n");
        }

        #pragma unroll
        for (int mt = 0; mt < 2; mt++) {
            float Sf[8][4];
            #pragma unroll
            for (int nt = 0; nt < 8; nt++) {
                float c0 = 0.f, c1 = 0.f, c2 = 0.f, c3 = 0.f;
                #pragma unroll
                for (int s = 0; s < 2; s++) {
                    uint32_t b0 = Kh[buf][nt * 8 + gi][s * 8 + ci];
                    uint32_t b1 = Kh[buf][nt * 8 + gi][s * 8 + ci + 4];
                    mma_f16(c0, c1, c2, c3,
                            qh[mt][s][0], qh[mt][s][1], qh[mt][s][2], qh[mt][s][3],
                            b0, b1);
                }
                Sf[nt][0] = c0; Sf[nt][1] = c1; Sf[nt][2] = c2; Sf[nt][3] = c3;
            }

            float mx0 = -1e30f, mx1 = -1e30f;
            #pragma unroll
            for (int nt = 0; nt < 8; nt++) {
                mx0 = fmaxf(mx0, fmaxf(Sf[nt][0], Sf[nt][1]));
                mx1 = fmaxf(mx1, fmaxf(Sf[nt][2], Sf[nt][3]));
            }
            mx0 = fmaxf(mx0, __shfl_xor_sync(0xffffffffu, mx0, 1));
            mx0 = fmaxf(mx0, __shfl_xor_sync(0xffffffffu, mx0, 2));
            mx1 = fmaxf(mx1, __shfl_xor_sync(0xffffffffu, mx1, 1));
            mx1 = fmaxf(mx1, __shfl_xor_sync(0xffffffffu, mx1, 2));

            float mn0 = fmaxf(mM[mt][0], mx0), mn1 = fmaxf(mM[mt][1], mx1);
            float corr0 = ex2(mM[mt][0] - mn0), corr1 = ex2(mM[mt][1] - mn1);
            float sum0 = 0.f, sum1 = 0.f;
            #pragma unroll
            for (int nt = 0; nt < 8; nt++) {
                Sf[nt][0] = ex2(Sf[nt][0] - mn0); sum0 += Sf[nt][0];
                Sf[nt][1] = ex2(Sf[nt][1] - mn0); sum0 += Sf[nt][1];
                Sf[nt][2] = ex2(Sf[nt][2] - mn1); sum1 += Sf[nt][2];
                Sf[nt][3] = ex2(Sf[nt][3] - mn1); sum1 += Sf[nt][3];
            }
            sum0 += __shfl_xor_sync(0xffffffffu, sum0, 1);
            sum0 += __shfl_xor_sync(0xffffffffu, sum0, 2);
            sum1 += __shfl_xor_sync(0xffffffffu, sum1, 1);
            sum1 += __shfl_xor_sync(0xffffffffu, sum1, 2);
            lS[mt][0] = lS[mt][0] * corr0 + sum0;
            lS[mt][1] = lS[mt][1] * corr1 + sum1;
            mM[mt][0] = mn0; mM[mt][1] = mn1;

            #pragma unroll
            for (int n = 0; n < 4; n++) {
                O[mt][n][0] *= corr0; O[mt][n][1] *= corr0;
                O[mt][n][2] *= corr1; O[mt][n][3] *= corr1;
            }

            #pragma unroll
            for (int s = 0; s < 4; s++) {
                uint32_t a0 = pack_h2(Sf[2 * s][0],     Sf[2 * s][1]);
                uint32_t a1 = pack_h2(Sf[2 * s][2],     Sf[2 * s][3]);
                uint32_t a2 = pack_h2(Sf[2 * s + 1][0], Sf[2 * s + 1][1]);
                uint32_t a3 = pack_h2(Sf[2 * s + 1][2], Sf[2 * s + 1][3]);
                int mi = lane >> 3;
                int key = s * 16 + (mi & 1) * 8 + (lane & 7);
                #pragma unroll
                for (int db = 0; db < 2; db++) {
                    int dh0 = db * 16 + (mi >> 1) * 8;
                    uint32_t B0, B1, B2, B3;
                    ldsm_x4_trans(B0, B1, B2, B3, smem_u32(&Vsh[buf][key][dh0]));
                    mma_f16(O[mt][2 * db][0],     O[mt][2 * db][1],
                            O[mt][2 * db][2],     O[mt][2 * db][3],
                            a0, a1, a2, a3, B0, B1);
                    mma_f16(O[mt][2 * db + 1][0], O[mt][2 * db + 1][1],
                            O[mt][2 * db + 1][2], O[mt][2 * db + 1][3],
                            a0, a1, a2, a3, B2, B3);
                }
            }
        }
    }

    // Epilogue: out = O/l + lf, packed bf16 hi/lo for O-projection
    const float* lfp = lf + ((size_t)(b * NP + qbase)) * DD + h * DH;
    uint32_t* th = tmphi + ((size_t)(b * NP + qbase)) * 128 + h * (DH / 2);
    uint32_t* tl = tmplo + ((size_t)(b * NP + qbase)) * 128 + h * (DH / 2);
    #pragma unroll
    for (int mt = 0; mt < 2; mt++) {
        float inv0 = 1.0f / lS[mt][0], inv1 = 1.0f / lS[mt][1];
        #pragma unroll
        for (int n = 0; n < 4; n++) {
            int row0 = mt * 16 + gi, row1 = row0 + 8;
            int col = n * 8 + 2 * ci;
            float2 L0 = *(const float2*)(lfp + (size_t)row0 * DD + col);
            float2 L1 = *(const float2*)(lfp + (size_t)row1 * DD + col);
            float a0 = O[mt][n][0] * inv0 + L0.x;
            float a1 = O[mt][n][1] * inv0 + L0.y;
            float b0 = O[mt][n][2] * inv1 + L1.x;
            float b1 = O[mt][n][3] * inv1 + L1.y;
            uint32_t hi, lo;
            split_pack_bf2(a0, a1, hi, lo);
            th[(size_t)row0 * 128 + col / 2] = hi;
            tl[(size_t)row0 * 128 + col / 2] = lo;
            split_pack_bf2(b0, b1, hi, lo);
            th[(size_t)row1 * 128 + col / 2] = hi;
            tl[(size_t)row1 * 128 + col / 2] = lo;
        }
    }
}

// ---------------------------------------------------------------------------
extern "C" void kernel_launch(void* const* d_in, const int* in_sizes, int n_in,
                              void* d_out, int out_size) {
    const float* local_feat  = (const float*)d_in[0];
    const float* global_feat = (const float*)d_in[1];
    const float* Wq = (const float*)d_in[2];
    const float* bq = (const float*)d_in[3];
    const float* Wk = (const float*)d_in[4];
    const float* bk = (const float*)d_in[5];
    const float* Wv = (const float*)d_in[6];
    const float* bv = (const float*)d_in[7];
    const float* Wo = (const float*)d_in[8];
    const float* bo = (const float*)d_in[9];
    float* out = (float*)d_out;

    float* base = nullptr;
    cudaGetSymbolAddress((void**)&base, g_scratch);
    float* lf = base;
    __half* q  = (__half*)(lf + LF_ELEMS);
    __half* kv = q + LF_ELEMS;
    uint32_t* lfhi  = (uint32_t*)(kv + 8 * 1024 * 1024);
    uint32_t* lflo  = lfhi  + LF_ELEMS / 2;
    uint32_t* gfhi  = lflo  + LF_ELEMS / 2;
    uint32_t* gflo  = gfhi  + GF_ELEMS / 2;
    uint32_t* tmphi = gflo  + GF_ELEMS / 2;
    uint32_t* tmplo = tmphi + LF_ELEMS / 2;
    uint32_t* wqh   = tmplo + LF_ELEMS / 2;
    uint32_t* wql   = wqh + 32768;
    uint32_t* wkvh  = wql + 32768;
    uint32_t* wkvl  = wkvh + 65536;
    uint32_t* woh   = wkvl + 65536;
    uint32_t* wol   = woh + 32768;
    float*    bkv   = (float*)(wol + 32768);

    split_w_kernel<<<dim3(128, 4), 256>>>(Wq, Wk, Wv, Wo, bk, bv,
                                          wqh, wql, wkvh, wkvl, woh, wol, bkv);
    pe_local_kernel<<<(int)(LF_ELEMS / 2 / 256), 256>>>(local_feat, lf, lfhi, lflo);
    pe_global_kernel<<<dim3(HWT / 32, DD / 32, NB), 256>>>(global_feat, gfhi, gflo);

    gemm_qkv_kernel<<<576, 256>>>(lfhi, lflo, gfhi, gflo,
                                  wqh, wql, wkvh, wkvl, bq, bkv, q, kv);

    flash_mma_kernel<<<dim3(NP / 256, HEADS, NB), 256>>>(q, kv, lf, tmphi, tmplo);

    gemm_o_kernel<<<dim3(2, (NB * NP) / 128), 256>>>(tmphi, tmplo, woh, wol, bo, out);
}

// round 12
// speedup vs baseline: 1.8670x; 1.1902x over previous
#include <cuda_runtime.h>
#include <cuda_fp16.h>
#include <cuda_bf16.h>
#include <stdint.h>
#include <stddef.h>
#include <math.h>

#define NB   4
#define NP   1024
#define DD   256
#define HWT  4096
#define HEADS 8
#define DH   32

#define LF_ELEMS  ((size_t)NB*NP*DD)   // 1M
#define GF_ELEMS  ((size_t)NB*HWT*DD)  // 4M
__device__ float g_scratch[17 * 1024 * 1024];

#define LN10K 9.210340371976184f
// 1/sqrt(32) * log2(e): K prescale so scores are in exp2 domain
#define KSCALE_EX2 0.25503482f
#define ONES_H2 0x3C003C00u

// ---------------------------------------------------------------------------
// helpers
// ---------------------------------------------------------------------------
__device__ __forceinline__ void cp16(uint32_t dst, const void* src) {
    asm volatile("cp.async.cg.shared.global [%0], [%1], 16;\n" :: "r"(dst), "l"(src));
}
__device__ __forceinline__ uint32_t smem_u32(const void* p) {
    return (uint32_t)__cvta_generic_to_shared(p);
}
__device__ __forceinline__ void mma_bf16(float& c0, float& c1, float& c2, float& c3,
                                         const uint32_t a[4], uint32_t b0, uint32_t b1) {
    asm volatile(
        "mma.sync.aligned.m16n8k16.row.col.f32.bf16.bf16.f32 "
        "{%0,%1,%2,%3}, {%4,%5,%6,%7}, {%8,%9}, {%0,%1,%2,%3};\n"
        : "+f"(c0), "+f"(c1), "+f"(c2), "+f"(c3)
        : "r"(a[0]), "r"(a[1]), "r"(a[2]), "r"(a[3]), "r"(b0), "r"(b1));
}
__device__ __forceinline__ void mma_f16(float& c0, float& c1, float& c2, float& c3,
                                        uint32_t a0, uint32_t a1, uint32_t a2, uint32_t a3,
                                        uint32_t b0, uint32_t b1) {
    asm volatile(
        "mma.sync.aligned.m16n8k16.row.col.f32.f16.f16.f32 "
        "{%0,%1,%2,%3}, {%4,%5,%6,%7}, {%8,%9}, {%0,%1,%2,%3};\n"
        : "+f"(c0), "+f"(c1), "+f"(c2), "+f"(c3)
        : "r"(a0), "r"(a1), "r"(a2), "r"(a3), "r"(b0), "r"(b1));
}
__device__ __forceinline__ void ldsm_x4(uint32_t& r0, uint32_t& r1,
                                        uint32_t& r2, uint32_t& r3, uint32_t addr) {
    asm volatile("ldmatrix.sync.aligned.m8n8.x4.shared.b16 {%0,%1,%2,%3}, [%4];\n"
                 : "=r"(r0), "=r"(r1), "=r"(r2), "=r"(r3) : "r"(addr));
}
__device__ __forceinline__ void ldsm_x4_trans(uint32_t& r0, uint32_t& r1,
                                              uint32_t& r2, uint32_t& r3, uint32_t addr) {
    asm volatile("ldmatrix.sync.aligned.m8n8.x4.trans.shared.b16 {%0,%1,%2,%3}, [%4];\n"
                 : "=r"(r0), "=r"(r1), "=r"(r2), "=r"(r3) : "r"(addr));
}
__device__ __forceinline__ float ex2(float x) {
    float r;
    asm("ex2.approx.f32 %0, %1;" : "=f"(r) : "f"(x));
    return r;
}
__device__ __forceinline__ uint32_t h2ex2(uint32_t x) {
    uint32_t r;
    asm("ex2.approx.f16x2 %0, %1;" : "=r"(r) : "r"(x));
    return r;
}
__device__ __forceinline__ uint32_t pack_h2(float lo, float hi) {
    __half2 h = __floats2half2_rn(lo, hi);
    return *reinterpret_cast<uint32_t*>(&h);
}
__device__ __forceinline__ void split_pack_bf2(float a, float b, uint32_t& hi, uint32_t& lo) {
    __nv_bfloat16 ah = __float2bfloat16_rn(a);
    __nv_bfloat16 bh = __float2bfloat16_rn(b);
    float ar = a - __bfloat162float(ah);
    float br = b - __bfloat162float(bh);
    __nv_bfloat162 h2 = __halves2bfloat162(ah, bh);
    __nv_bfloat162 l2 = __floats2bfloat162_rn(ar, br);
    hi = *reinterpret_cast<uint32_t*>(&h2);
    lo = *reinterpret_cast<uint32_t*>(&l2);
}

// ---------------------------------------------------------------------------
// PE local
// ---------------------------------------------------------------------------
__global__ void pe_local_kernel(const float* __restrict__ in, float* __restrict__ lf,
                                uint32_t* __restrict__ lfhi, uint32_t* __restrict__ lflo) {
    int idx = blockIdx.x * blockDim.x + threadIdx.x;
    if (idx >= (int)(LF_ELEMS / 2)) return;
    int d2 = idx & 127;
    int p  = (idx >> 7) & (NP - 1);
    int d  = 2 * d2;
    float div = expf((float)d * (-LN10K / 256.0f));
    float x = (float)(p & 31) * (1.0f / 31.0f);
    float y = (float)(p >> 5) * (1.0f / 31.0f);
    float2 v = *(const float2*)(in + (size_t)idx * 2);
    float v0 = v.x + sinf(x * div);
    float v1 = v.y + cosf(y * div);
    *(float2*)(lf + (size_t)idx * 2) = make_float2(v0, v1);
    uint32_t hi, lo;
    split_pack_bf2(v0, v1, hi, lo);
    lfhi[idx] = hi;
    lflo[idx] = lo;
}

// ---------------------------------------------------------------------------
// PE global: transpose + PE -> packed bf16 hi/lo
// ---------------------------------------------------------------------------
__global__ __launch_bounds__(256) void pe_global_kernel(const float* __restrict__ in,
                                                        uint32_t* __restrict__ gfhi,
                                                        uint32_t* __restrict__ gflo) {
    __shared__ float tile[32][33];
    const int tid = threadIdx.x;
    const int tx = tid & 31;
    const int ty = tid >> 5;
    const int t0 = blockIdx.x << 5;
    const int d0 = blockIdx.y << 5;
    const int b  = blockIdx.z;

    #pragma unroll
    for (int i = 0; i < 4; i++) {
        int d = d0 + ty + i * 8;
        tile[ty + i * 8][tx] = in[((size_t)b * DD + d) * HWT + t0 + tx];
    }
    __syncthreads();

    const int dp = tid & 15;
    #pragma unroll
    for (int i = 0; i < 2; i++) {
        int tr = (tid >> 4) + i * 16;
        int t = t0 + tr;
        int d = d0 + 2 * dp;
        float div = expf((float)d * (-LN10K / 256.0f));
        float x = (float)(t & 63) * (1.0f / 63.0f);
        float y = (float)(t >> 6) * (1.0f / 63.0f);
        float v0 = tile[2 * dp][tr]     + sinf(x * div);
        float v1 = tile[2 * dp + 1][tr] + cosf(y * div);
        uint32_t hi, lo;
        split_pack_bf2(v0, v1, hi, lo);
        size_t o = ((size_t)b * HWT + t) * 128 + d0 / 2 + dp;
        gfhi[o] = hi;
        gflo[o] = lo;
    }
}

// ---------------------------------------------------------------------------
// Split weights (Wk,Wv stacked); bias bk||bv
// ---------------------------------------------------------------------------
__global__ void split_w_kernel(const float* __restrict__ Wq, const float* __restrict__ Wk,
                               const float* __restrict__ Wv, const float* __restrict__ Wo,
                               const float* __restrict__ bk, const float* __restrict__ bv,
                               uint32_t* __restrict__ wqh, uint32_t* __restrict__ wql,
                               uint32_t* __restrict__ wkvh, uint32_t* __restrict__ wkvl,
                               uint32_t* __restrict__ woh, uint32_t* __restrict__ wol,
                               float* __restrict__ bkv) {
    int idx = blockIdx.x * blockDim.x + threadIdx.x;
    int m = blockIdx.y;
    const float* W; uint32_t *oh, *ol;
    if (m == 0)      { W = Wq; oh = wqh;          ol = wql;          }
    else if (m == 1) { W = Wk; oh = wkvh;         ol = wkvl;         }
    else if (m == 2) { W = Wv; oh = wkvh + 32768; ol = wkvl + 32768; }
    else             { W = Wo; oh = woh;          ol = wol;          }
    float2 v = *(const float2*)(W + (size_t)idx * 2);
    uint32_t hi, lo;
    split_pack_bf2(v.x, v.y, hi, lo);
    oh[idx] = hi;
    ol[idx] = lo;
    if (m == 0 && idx < 512)
        bkv[idx] = (idx < 256) ? bk[idx] : bv[idx - 256];
}

// ---------------------------------------------------------------------------
// bf16x3 GEMM body (128x128 tile), ldmatrix fragment loads.
// ---------------------------------------------------------------------------
struct GemmArgs {
    const uint32_t *Ahi, *Alo, *Whi, *Wlo;
    const float* bias;
    void* Cout;
    int mBase, nBase, ldc;
    float scale;
    int outhalf;
};

__device__ __forceinline__ void gemm_tile_body(const GemmArgs& ga) {
    __shared__ uint32_t sAh[2][128][12];
    __shared__ uint32_t sAl[2][128][12];
    __shared__ uint32_t sWh[2][128][12];
    __shared__ uint32_t sWl[2][128][12];

    const int tid  = threadIdx.x;
    const int warp = tid >> 5;
    const int lane = tid & 31;
    const int gi = lane >> 2;
    const int ci = lane & 3;
    const int wm = (warp & 3) << 5;
    const int wn = (warp >> 2) << 6;

    const int arr = tid >> 6;
    const int r0 = (tid & 63) * 2;
    const uint32_t* gsrc = (arr == 0) ? ga.Ahi + (size_t)ga.mBase * 128
                         : (arr == 1) ? ga.Alo + (size_t)ga.mBase * 128
                         : (arr == 2) ? ga.Whi + (size_t)ga.nBase * 128
                                      : ga.Wlo + (size_t)ga.nBase * 128;
    uint32_t sdst = (arr == 0) ? smem_u32(&sAh[0][0][0])
                  : (arr == 1) ? smem_u32(&sAl[0][0][0])
                  : (arr == 2) ? smem_u32(&sWh[0][0][0])
                               : smem_u32(&sWl[0][0][0]);
    const uint32_t stageBytes = 128 * 12 * 4;

    // ldmatrix per-lane byte offsets (within a stage)
    const int l = lane;
    const uint32_t offA0 = ((uint32_t)((wm +      (l & 15)) * 12 + (l >> 4) * 4)) * 4;
    const uint32_t offA1 = ((uint32_t)((wm + 16 + (l & 15)) * 12 + (l >> 4) * 4)) * 4;
    const uint32_t offB  = ((uint32_t)((wn + (l & 7) + (l >> 4) * 8) * 12
                                       + ((l >> 3) & 1) * 4)) * 4;

    float acc[2][8][4];
    #pragma unroll
    for (int mt = 0; mt < 2; mt++)
        #pragma unroll
        for (int nt = 0; nt < 8; nt++)
            #pragma unroll
            for (int i = 0; i < 4; i++) acc[mt][nt][i] = 0.0f;

    #pragma unroll
    for (int j = 0; j < 4; j++) {
        int row = r0 + (j >> 1), half = j & 1;
        cp16(sdst + (row * 12 + half * 4) * 4, gsrc + (size_t)row * 128 + half * 4);
    }
    asm volatile("cp.async.commit_group;\n");

    const uint32_t bAh = smem_u32(&sAh[0][0][0]);
    const uint32_t bAl = smem_u32(&sAl[0][0][0]);
    const uint32_t bWh = smem_u32(&sWh[0][0][0]);
    const uint32_t bWl = smem_u32(&sWl[0][0][0]);

    for (int kt = 0; kt < 16; kt++) {
        const int buf = kt & 1;
        if (kt < 15) {
            const int k0u = (kt + 1) * 8;
            uint32_t d2 = sdst + (buf ^ 1) * stageBytes;
            #pragma unroll
            for (int j = 0; j < 4; j++) {
                int row = r0 + (j >> 1), half = j & 1;
                cp16(d2 + (row * 12 + half * 4) * 4, gsrc + (size_t)row * 128 + k0u + half * 4);
            }
            asm volatile("cp.async.commit_group;\n");
            asm volatile("cp.async.wait_group 1;\n");
        } else {
            asm volatile("cp.async.wait_group 0;\n");
        }
        __syncthreads();

        const uint32_t so = buf * stageBytes;
        uint32_t ah[2][4], al[2][4];
        ldsm_x4(ah[0][0], ah[0][1], ah[0][2], ah[0][3], bAh + so + offA0);
        ldsm_x4(ah[1][0], ah[1][1], ah[1][2], ah[1][3], bAh + so + offA1);
        ldsm_x4(al[0][0], al[0][1], al[0][2], al[0][3], bAl + so + offA0);
        ldsm_x4(al[1][0], al[1][1], al[1][2], al[1][3], bAl + so + offA1);

        #pragma unroll
        for (int p = 0; p < 4; p++) {
            uint32_t bh[4], bl[4];
            ldsm_x4(bh[0], bh[1], bh[2], bh[3], bWh + so + offB + p * 768);
            ldsm_x4(bl[0], bl[1], bl[2], bl[3], bWl + so + offB + p * 768);
            #pragma unroll
            for (int e = 0; e < 2; e++) {
                int nt = 2 * p + e;
                uint32_t bh0 = bh[2 * e], bh1 = bh[2 * e + 1];
                uint32_t bl0 = bl[2 * e], bl1 = bl[2 * e + 1];
                #pragma unroll
                for (int mt = 0; mt < 2; mt++) {
                    mma_bf16(acc[mt][nt][0], acc[mt][nt][1], acc[mt][nt][2], acc[mt][nt][3],
                             al[mt], bh0, bh1);
                    mma_bf16(acc[mt][nt][0], acc[mt][nt][1], acc[mt][nt][2], acc[mt][nt][3],
                             ah[mt], bl0, bl1);
                    mma_bf16(acc[mt][nt][0], acc[mt][nt][1], acc[mt][nt][2], acc[mt][nt][3],
                             ah[mt], bh0, bh1);
                }
            }
        }
        __syncthreads();
    }

    #pragma unroll
    for (int mt = 0; mt < 2; mt++) {
        #pragma unroll
        for (int nt = 0; nt < 8; nt++) {
            int ncol = ga.nBase + wn + nt * 8 + 2 * ci;
            float2 bs = *(const float2*)(ga.bias + ncol);
            int row = ga.mBase + wm + mt * 16 + gi;
            float c00 = (acc[mt][nt][0] + bs.x) * ga.scale;
            float c01 = (acc[mt][nt][1] + bs.y) * ga.scale;
            float c10 = (acc[mt][nt][2] + bs.x) * ga.scale;
            float c11 = (acc[mt][nt][3] + bs.y) * ga.scale;
            if (ga.outhalf) {
                uint32_t* C = (uint32_t*)ga.Cout;
                C[(size_t)row * (ga.ldc / 2) + ncol / 2]       = pack_h2(c00, c01);
                C[(size_t)(row + 8) * (ga.ldc / 2) + ncol / 2] = pack_h2(c10, c11);
            } else {
                float* C = (float*)ga.Cout;
                *(float2*)(C + (size_t)row * 256 + ncol)       = make_float2(c00, c01);
                *(float2*)(C + (size_t)(row + 8) * 256 + ncol) = make_float2(c10, c11);
            }
        }
    }
}

// Merged Q + KV projection: blocks [0,512) do KV, [512,576) do Q.
__global__ __launch_bounds__(256) void gemm_qkv_kernel(
    const uint32_t* __restrict__ lfhi, const uint32_t* __restrict__ lflo,
    const uint32_t* __restrict__ gfhi, const uint32_t* __restrict__ gflo,
    const uint32_t* __restrict__ wqh,  const uint32_t* __restrict__ wql,
    const uint32_t* __restrict__ wkvh, const uint32_t* __restrict__ wkvl,
    const float* __restrict__ bq, const float* __restrict__ bkv,
    __half* __restrict__ qout, __half* __restrict__ kvout)
{
    GemmArgs ga;
    ga.outhalf = 1;
    int bid = blockIdx.x;
    if (bid < 512) {
        int bx = bid & 3, by = bid >> 2;
        ga.Ahi = gfhi; ga.Alo = gflo;
        ga.Whi = wkvh; ga.Wlo = wkvl;
        ga.bias = bkv; ga.Cout = kvout;
        ga.mBase = by << 7; ga.nBase = bx << 7; ga.ldc = 512;
        ga.scale = (ga.nBase < 256) ? KSCALE_EX2 : 1.0f;
    } else {
        int q = bid - 512;
        int bx = q & 1, by = q >> 1;
        ga.Ahi = lfhi; ga.Alo = lflo;
        ga.Whi = wqh;  ga.Wlo = wql;
        ga.bias = bq;  ga.Cout = qout;
        ga.mBase = by << 7; ga.nBase = bx << 7; ga.ldc = 256;
        ga.scale = 1.0f;
    }
    gemm_tile_body(ga);
}

// ---------------------------------------------------------------------------
// O projection: 64x128 tiles (grid 2 x 64 = 128 blocks), fp32 out.
// ---------------------------------------------------------------------------
__global__ __launch_bounds__(256) void gemm_o_kernel(
    const uint32_t* __restrict__ Ahi, const uint32_t* __restrict__ Alo,
    const uint32_t* __restrict__ Whi, const uint32_t* __restrict__ Wlo,
    const float* __restrict__ bias, float* __restrict__ C)
{
    __shared__ uint32_t sAh[2][64][12];
    __shared__ uint32_t sAl[2][64][12];
    __shared__ uint32_t sWh[2][128][12];
    __shared__ uint32_t sWl[2][128][12];

    const int tid  = threadIdx.x;
    const int warp = tid >> 5;
    const int lane = tid & 31;
    const int gi = lane >> 2;
    const int ci = lane & 3;
    const int mBase = (int)blockIdx.y << 6;
    const int nBase = (int)blockIdx.x << 7;
    const int wm = (warp & 3) << 4;    // 0,16,32,48
    const int wn = (warp >> 2) << 6;   // 0,64

    const int arr = tid >> 6;
    const int t64 = tid & 63;
    const uint32_t aStage = 64 * 12 * 4;
    const uint32_t wStage = 128 * 12 * 4;

    const int l = lane;
    const uint32_t offA = ((uint32_t)((wm + (l & 15)) * 12 + (l >> 4) * 4)) * 4;
    const uint32_t offB = ((uint32_t)((wn + (l & 7) + (l >> 4) * 8) * 12
                                      + ((l >> 3) & 1) * 4)) * 4;
    const uint32_t bAh = smem_u32(&sAh[0][0][0]);
    const uint32_t bAl = smem_u32(&sAl[0][0][0]);
    const uint32_t bWh = smem_u32(&sWh[0][0][0]);
    const uint32_t bWl = smem_u32(&sWl[0][0][0]);

    float acc[8][4];
    #pragma unroll
    for (int nt = 0; nt < 8; nt++)
        #pragma unroll
        for (int i = 0; i < 4; i++) acc[nt][i] = 0.0f;

    // stage copy helper (k0u = u32 column offset)
    #define O_COPY(st, k0u)                                                          \
        do {                                                                         \
            if (arr == 0) {                                                          \
                cp16(bAh + (st) * aStage + (t64 * 12) * 4,                           \
                     Ahi + (size_t)(mBase + t64) * 128 + (k0u));                     \
                cp16(bAh + (st) * aStage + (t64 * 12 + 4) * 4,                       \
                     Ahi + (size_t)(mBase + t64) * 128 + (k0u) + 4);                 \
            } else if (arr == 1) {                                                   \
                cp16(bAl + (st) * aStage + (t64 * 12) * 4,                           \
                     Alo + (size_t)(mBase + t64) * 128 + (k0u));                     \
                cp16(bAl + (st) * aStage + (t64 * 12 + 4) * 4,                       \
                     Alo + (size_t)(mBase + t64) * 128 + (k0u) + 4);                 \
            } else if (arr == 2) {                                                   \
                _Pragma("unroll")                                                    \
                for (int j = 0; j < 4; j++) {                                        \
                    int row = t64 * 2 + (j >> 1), half = j & 1;                      \
                    cp16(bWh + (st) * wStage + (row * 12 + half * 4) * 4,            \
                         Whi + (size_t)(nBase + row) * 128 + (k0u) + half * 4);      \
                }                                                                    \
            } else {                                                                 \
                _Pragma("unroll")                                                    \
                for (int j = 0; j < 4; j++) {                                        \
                    int row = t64 * 2 + (j >> 1), half = j & 1;                      \
                    cp16(bWl + (st) * wStage + (row * 12 + half * 4) * 4,            \
                         Wlo + (size_t)(nBase + row) * 128 + (k0u) + half * 4);      \
                }                                                                    \
            }                                                                        \
        } while (0)

    O_COPY(0, 0);
    asm volatile("cp.async.commit_group;\n");

    for (int kt = 0; kt < 16; kt++) {
        const int buf = kt & 1;
        if (kt < 15) {
            O_COPY(buf ^ 1, (kt + 1) * 8);
            asm volatile("cp.async.commit_group;\n");
            asm volatile("cp.async.wait_group 1;\n");
        } else {
            asm volatile("cp.async.wait_group 0;\n");
        }
        __syncthreads();

        uint32_t ah[4], al[4];
        ldsm_x4(ah[0], ah[1], ah[2], ah[3], bAh + buf * aStage + offA);
        ldsm_x4(al[0], al[1], al[2], al[3], bAl + buf * aStage + offA);

        #pragma unroll
        for (int p = 0; p < 4; p++) {
            uint32_t bh[4], bl[4];
            ldsm_x4(bh[0], bh[1], bh[2], bh[3], bWh + buf * wStage + offB + p * 768);
            ldsm_x4(bl[0], bl[1], bl[2], bl[3], bWl + buf * wStage + offB + p * 768);
            #pragma unroll
            for (int e = 0; e < 2; e++) {
                int nt = 2 * p + e;
                mma_bf16(acc[nt][0], acc[nt][1], acc[nt][2], acc[nt][3],
                         al, bh[2 * e], bh[2 * e + 1]);
                mma_bf16(acc[nt][0], acc[nt][1], acc[nt][2], acc[nt][3],
                         ah, bl[2 * e], bl[2 * e + 1]);
                mma_bf16(acc[nt][0], acc[nt][1], acc[nt][2], acc[nt][3],
                         ah, bh[2 * e], bh[2 * e + 1]);
            }
        }
        __syncthreads();
    }
    #undef O_COPY

    #pragma unroll
    for (int nt = 0; nt < 8; nt++) {
        int ncol = nBase + wn + nt * 8 + 2 * ci;
        float2 bs = *(const float2*)(bias + ncol);
        int row = mBase + wm + gi;
        *(float2*)(C + (size_t)row * 256 + ncol) =
            make_float2(acc[nt][0] + bs.x, acc[nt][1] + bs.y);
        *(float2*)(C + (size_t)(row + 8) * 256 + ncol) =
            make_float2(acc[nt][2] + bs.x, acc[nt][3] + bs.y);
    }
}

// ---------------------------------------------------------------------------
// Flash attention: 256 queries/block (8 warps x 32), KV tile 64, double buffer.
// Scores in exp2 domain; P via ex2.approx.f16x2; row-sum l via ones-MMA.
// ---------------------------------------------------------------------------
__global__ __launch_bounds__(256, 2) void flash_mma_kernel(
    const __half* __restrict__ q, const __half* __restrict__ kv,
    const float* __restrict__ lf,
    uint32_t* __restrict__ tmphi, uint32_t* __restrict__ tmplo)
{
    __shared__ uint32_t Kh[2][64][20];
    __shared__ __half   Vsh[2][64][40];

    const int tid  = threadIdx.x;
    const int warp = tid >> 5;
    const int lane = tid & 31;
    const int gi = lane >> 2;
    const int ci = lane & 3;
    const int b = blockIdx.z;
    const int h = blockIdx.y;
    const int qbase = (blockIdx.x << 8) + warp * 32;

    uint32_t qh[2][2][4];
    {
        const __half* qp = q + ((size_t)(b * NP + qbase)) * DD + h * DH;
        #pragma unroll
        for (int mt = 0; mt < 2; mt++)
            #pragma unroll
            for (int s = 0; s < 2; s++)
                #pragma unroll
                for (int r = 0; r < 4; r++) {
                    int row = mt * 16 + gi + (r & 1) * 8;
                    int col = s * 16 + 2 * ci + (r >> 1) * 8;
                    qh[mt][s][r] = *(const uint32_t*)(qp + (size_t)row * DD + col);
                }
    }

    float O[2][4][4];
    #pragma unroll
    for (int mt = 0; mt < 2; mt++)
        #pragma unroll
        for (int n = 0; n < 4; n++)
            #pragma unroll
            for (int i = 0; i < 4; i++) O[mt][n][i] = 0.0f;
    float Lc[2][4];       // l accumulators via ones-MMA: [mt][c]; c0=row gi, c2=row gi+8
    float mM[2][2];
    #pragma unroll
    for (int mt = 0; mt < 2; mt++) {
        Lc[mt][0] = Lc[mt][1] = Lc[mt][2] = Lc[mt][3] = 0.0f;
        mM[mt][0] = -1e30f; mM[mt][1] = -1e30f;
    }

    const __half* kbase = kv + (size_t)b * HWT * 512 + h * DH;
    const __half* vbase = kv + (size_t)b * HWT * 512 + 256 + h * DH;

    // ldmatrix offset for QK B-frags: 4 chunks (u32 0,4,8,12) of row nt*8+(l&7)
    const uint32_t offK = ((uint32_t)((lane & 7) * 20 + (lane >> 3) * 4)) * 4;
    const uint32_t kStage = 64 * 20 * 4;
    const uint32_t bK = smem_u32(&Kh[0][0][0]);

    {
        int key = tid >> 2, ch = tid & 3;
        cp16(smem_u32(&Kh[0][key][ch * 4]),  kbase + (size_t)key * 512 + ch * 8);
        cp16(smem_u32(&Vsh[0][key][ch * 8]), vbase + (size_t)key * 512 + ch * 8);
    }
    asm volatile("cp.async.commit_group;\n");

    for (int t = 0; t < 64; t++) {
        const int buf = t & 1;
        asm volatile("cp.async.wait_group 0;\n");
        __syncthreads();
        if (t < 63) {
            const size_t kv0 = (size_t)(t + 1) << 6;
            int key = tid >> 2, ch = tid & 3;
            cp16(smem_u32(&Kh[buf ^ 1][key][ch * 4]),
                 kbase + (kv0 + key) * 512 + ch * 8);
            cp16(smem_u32(&Vsh[buf ^ 1][key][ch * 8]),
                 vbase + (kv0 + key) * 512 + ch * 8);
            asm volatile("cp.async.commit_group;\n");
        }

        #pragma unroll
        for (int mt = 0; mt < 2; mt++) {
            float Sf[8][4];
            #pragma unroll
            for (int nt = 0; nt < 8; nt++) {
                uint32_t B0, B1, B2, B3;
                ldsm_x4(B0, B1, B2, B3, bK + buf * kStage + offK + nt * 640);
                float c0 = 0.f, c1 = 0.f, c2 = 0.f, c3 = 0.f;
                mma_f16(c0, c1, c2, c3,
                        qh[mt][0][0], qh[mt][0][1], qh[mt][0][2], qh[mt][0][3], B0, B1);
                mma_f16(c0, c1, c2, c3,
                        qh[mt][1][0], qh[mt][1][1], qh[mt][1][2], qh[mt][1][3], B2, B3);
                Sf[nt][0] = c0; Sf[nt][1] = c1; Sf[nt][2] = c2; Sf[nt][3] = c3;
            }

            float mx0 = -1e30f, mx1 = -1e30f;
            #pragma unroll
            for (int nt = 0; nt < 8; nt++) {
                mx0 = fmaxf(mx0, fmaxf(Sf[nt][0], Sf[nt][1]));
                mx1 = fmaxf(mx1, fmaxf(Sf[nt][2], Sf[nt][3]));
            }
            mx0 = fmaxf(mx0, __shfl_xor_sync(0xffffffffu, mx0, 1));
            mx0 = fmaxf(mx0, __shfl_xor_sync(0xffffffffu, mx0, 2));
            mx1 = fmaxf(mx1, __shfl_xor_sync(0xffffffffu, mx1, 1));
            mx1 = fmaxf(mx1, __shfl_xor_sync(0xffffffffu, mx1, 2));

            float mn0 = fmaxf(mM[mt][0], mx0), mn1 = fmaxf(mM[mt][1], mx1);
            float corr0 = ex2(mM[mt][0] - mn0), corr1 = ex2(mM[mt][1] - mn1);
            mM[mt][0] = mn0; mM[mt][1] = mn1;

            #pragma unroll
            for (int n = 0; n < 4; n++) {
                O[mt][n][0] *= corr0; O[mt][n][1] *= corr0;
                O[mt][n][2] *= corr1; O[mt][n][3] *= corr1;
            }
            Lc[mt][0] *= corr0; Lc[mt][1] *= corr0;
            Lc[mt][2] *= corr1; Lc[mt][3] *= corr1;

            #pragma unroll
            for (int s = 0; s < 4; s++) {
                uint32_t a0 = h2ex2(pack_h2(Sf[2 * s][0] - mn0,     Sf[2 * s][1] - mn0));
                uint32_t a1 = h2ex2(pack_h2(Sf[2 * s][2] - mn1,     Sf[2 * s][3] - mn1));
                uint32_t a2 = h2ex2(pack_h2(Sf[2 * s + 1][0] - mn0, Sf[2 * s + 1][1] - mn0));
                uint32_t a3 = h2ex2(pack_h2(Sf[2 * s + 1][2] - mn1, Sf[2 * s + 1][3] - mn1));

                // row-sum l accumulation (ones B-fragment)
                mma_f16(Lc[mt][0], Lc[mt][1], Lc[mt][2], Lc[mt][3],
                        a0, a1, a2, a3, ONES_H2, ONES_H2);

                int mi = lane >> 3;
                int key = s * 16 + (mi & 1) * 8 + (lane & 7);
                #pragma unroll
                for (int db = 0; db < 2; db++) {
                    int dh0 = db * 16 + (mi >> 1) * 8;
                    uint32_t B0, B1, B2, B3;
                    ldsm_x4_trans(B0, B1, B2, B3, smem_u32(&Vsh[buf][key][dh0]));
                    mma_f16(O[mt][2 * db][0],     O[mt][2 * db][1],
                            O[mt][2 * db][2],     O[mt][2 * db][3],
                            a0, a1, a2, a3, B0, B1);
                    mma_f16(O[mt][2 * db + 1][0], O[mt][2 * db + 1][1],
                            O[mt][2 * db + 1][2], O[mt][2 * db + 1][3],
                            a0, a1, a2, a3, B2, B3);
                }
            }
        }
    }

    // Epilogue: out = O/l + lf, packed bf16 hi/lo for O-projection
    const float* lfp = lf + ((size_t)(b * NP + qbase)) * DD + h * DH;
    uint32_t* th = tmphi + ((size_t)(b * NP + qbase)) * 128 + h * (DH / 2);
    uint32_t* tl = tmplo + ((size_t)(b * NP + qbase)) * 128 + h * (DH / 2);
    #pragma unroll
    for (int mt = 0; mt < 2; mt++) {
        float inv0 = 1.0f / Lc[mt][0], inv1 = 1.0f / Lc[mt][2];
        #pragma unroll
        for (int n = 0; n < 4; n++) {
            int row0 = mt * 16 + gi, row1 = row0 + 8;
            int col = n * 8 + 2 * ci;
            float2 L0 = *(const float2*)(lfp + (size_t)row0 * DD + col);
            float2 L1 = *(const float2*)(lfp + (size_t)row1 * DD + col);
            float a0 = O[mt][n][0] * inv0 + L0.x;
            float a1 = O[mt][n][1] * inv0 + L0.y;
            float b0 = O[mt][n][2] * inv1 + L1.x;
            float b1 = O[mt][n][3] * inv1 + L1.y;
            uint32_t hi, lo;
            split_pack_bf2(a0, a1, hi, lo);
            th[(size_t)row0 * 128 + col / 2] = hi;
            tl[(size_t)row0 * 128 + col / 2] = lo;
            split_pack_bf2(b0, b1, hi, lo);
            th[(size_t)row1 * 128 + col / 2] = hi;
            tl[(size_t)row1 * 128 + col / 2] = lo;
        }
    }
}

// ---------------------------------------------------------------------------
extern "C" void kernel_launch(void* const* d_in, const int* in_sizes, int n_in,
                              void* d_out, int out_size) {
    const float* local_feat  = (const float*)d_in[0];
    const float* global_feat = (const float*)d_in[1];
    const float* Wq = (const float*)d_in[2];
    const float* bq = (const float*)d_in[3];
    const float* Wk = (const float*)d_in[4];
    const float* bk = (const float*)d_in[5];
    const float* Wv = (const float*)d_in[6];
    const float* bv = (const float*)d_in[7];
    const float* Wo = (const float*)d_in[8];
    const float* bo = (const float*)d_in[9];
    float* out = (float*)d_out;

    float* base = nullptr;
    cudaGetSymbolAddress((void**)&base, g_scratch);
    float* lf = base;
    __half* q  = (__half*)(lf + LF_ELEMS);
    __half* kv = q + LF_ELEMS;
    uint32_t* lfhi  = (uint32_t*)(kv + 8 * 1024 * 1024);
    uint32_t* lflo  = lfhi  + LF_ELEMS / 2;
    uint32_t* gfhi  = lflo  + LF_ELEMS / 2;
    uint32_t* gflo  = gfhi  + GF_ELEMS / 2;
    uint32_t* tmphi = gflo  + GF_ELEMS / 2;
    uint32_t* tmplo = tmphi + LF_ELEMS / 2;
    uint32_t* wqh   = tmplo + LF_ELEMS / 2;
    uint32_t* wql   = wqh + 32768;
    uint32_t* wkvh  = wql + 32768;
    uint32_t* wkvl  = wkvh + 65536;
    uint32_t* woh   = wkvl + 65536;
    uint32_t* wol   = woh + 32768;
    float*    bkv   = (float*)(wol + 32768);

    split_w_kernel<<<dim3(128, 4), 256>>>(Wq, Wk, Wv, Wo, bk, bv,
                                          wqh, wql, wkvh, wkvl, woh, wol, bkv);
    pe_local_kernel<<<(int)(LF_ELEMS / 2 / 256), 256>>>(local_feat, lf, lfhi, lflo);
    pe_global_kernel<<<dim3(HWT / 32, DD / 32, NB), 256>>>(global_feat, gfhi, gflo);

    gemm_qkv_kernel<<<576, 256>>>(lfhi, lflo, gfhi, gflo,
                                  wqh, wql, wkvh, wkvl, bq, bkv, q, kv);

    flash_mma_kernel<<<dim3(NP / 256, HEADS, NB), 256>>>(q, kv, lf, tmphi, tmplo);

    gemm_o_kernel<<<dim3(2, 64), 256>>>(tmphi, tmplo, woh, wol, bo, out);
}

// round 16
// speedup vs baseline: 1.9816x; 1.0614x over previous
#include <cuda_runtime.h>
#include <cuda_fp16.h>
#include <cuda_bf16.h>
#include <stdint.h>
#include <stddef.h>
#include <math.h>

#define NB   4
#define NP   1024
#define DD   256
#define HWT  4096
#define HEADS 8
#define DH   32

#define LF_ELEMS  ((size_t)NB*NP*DD)   // 1M
#define GF_ELEMS  ((size_t)NB*HWT*DD)  // 4M
__device__ float g_scratch[17 * 1024 * 1024];

#define LN10K 9.210340371976184f
// 1/sqrt(32) * log2(e): K prescale so scores are in exp2 domain
#define KSCALE_EX2 0.25503482f
#define ONES_H2 0x3C003C00u

// ---------------------------------------------------------------------------
// helpers
// ---------------------------------------------------------------------------
__device__ __forceinline__ void cp16(uint32_t dst, const void* src) {
    asm volatile("cp.async.cg.shared.global [%0], [%1], 16;\n" :: "r"(dst), "l"(src));
}
__device__ __forceinline__ uint32_t smem_u32(const void* p) {
    return (uint32_t)__cvta_generic_to_shared(p);
}
__device__ __forceinline__ void mma_bf16(float& c0, float& c1, float& c2, float& c3,
                                         const uint32_t a[4], uint32_t b0, uint32_t b1) {
    asm volatile(
        "mma.sync.aligned.m16n8k16.row.col.f32.bf16.bf16.f32 "
        "{%0,%1,%2,%3}, {%4,%5,%6,%7}, {%8,%9}, {%0,%1,%2,%3};\n"
        : "+f"(c0), "+f"(c1), "+f"(c2), "+f"(c3)
        : "r"(a[0]), "r"(a[1]), "r"(a[2]), "r"(a[3]), "r"(b0), "r"(b1));
}
__device__ __forceinline__ void mma_f16(float& c0, float& c1, float& c2, float& c3,
                                        uint32_t a0, uint32_t a1, uint32_t a2, uint32_t a3,
                                        uint32_t b0, uint32_t b1) {
    asm volatile(
        "mma.sync.aligned.m16n8k16.row.col.f32.f16.f16.f32 "
        "{%0,%1,%2,%3}, {%4,%5,%6,%7}, {%8,%9}, {%0,%1,%2,%3};\n"
        : "+f"(c0), "+f"(c1), "+f"(c2), "+f"(c3)
        : "r"(a0), "r"(a1), "r"(a2), "r"(a3), "r"(b0), "r"(b1));
}
__device__ __forceinline__ void ldsm_x4(uint32_t& r0, uint32_t& r1,
                                        uint32_t& r2, uint32_t& r3, uint32_t addr) {
    asm volatile("ldmatrix.sync.aligned.m8n8.x4.shared.b16 {%0,%1,%2,%3}, [%4];\n"
                 : "=r"(r0), "=r"(r1), "=r"(r2), "=r"(r3) : "r"(addr));
}
__device__ __forceinline__ void ldsm_x4_trans(uint32_t& r0, uint32_t& r1,
                                              uint32_t& r2, uint32_t& r3, uint32_t addr) {
    asm volatile("ldmatrix.sync.aligned.m8n8.x4.trans.shared.b16 {%0,%1,%2,%3}, [%4];\n"
                 : "=r"(r0), "=r"(r1), "=r"(r2), "=r"(r3) : "r"(addr));
}
__device__ __forceinline__ float ex2(float x) {
    float r;
    asm("ex2.approx.f32 %0, %1;" : "=f"(r) : "f"(x));
    return r;
}
__device__ __forceinline__ uint32_t h2ex2(uint32_t x) {
    uint32_t r;
    asm("ex2.approx.f16x2 %0, %1;" : "=r"(r) : "r"(x));
    return r;
}
__device__ __forceinline__ uint32_t pack_h2(float lo, float hi) {
    __half2 h = __floats2half2_rn(lo, hi);
    return *reinterpret_cast<uint32_t*>(&h);
}
__device__ __forceinline__ void split_pack_bf2(float a, float b, uint32_t& hi, uint32_t& lo) {
    __nv_bfloat16 ah = __float2bfloat16_rn(a);
    __nv_bfloat16 bh = __float2bfloat16_rn(b);
    float ar = a - __bfloat162float(ah);
    float br = b - __bfloat162float(bh);
    __nv_bfloat162 h2 = __halves2bfloat162(ah, bh);
    __nv_bfloat162 l2 = __floats2bfloat162_rn(ar, br);
    hi = *reinterpret_cast<uint32_t*>(&h2);
    lo = *reinterpret_cast<uint32_t*>(&l2);
}

// ---------------------------------------------------------------------------
// PE local
// ---------------------------------------------------------------------------
__global__ void pe_local_kernel(const float* __restrict__ in, float* __restrict__ lf,
                                uint32_t* __restrict__ lfhi, uint32_t* __restrict__ lflo) {
    int idx = blockIdx.x * blockDim.x + threadIdx.x;
    if (idx >= (int)(LF_ELEMS / 2)) return;
    int d2 = idx & 127;
    int p  = (idx >> 7) & (NP - 1);
    int d  = 2 * d2;
    float div = expf((float)d * (-LN10K / 256.0f));
    float x = (float)(p & 31) * (1.0f / 31.0f);
    float y = (float)(p >> 5) * (1.0f / 31.0f);
    float2 v = *(const float2*)(in + (size_t)idx * 2);
    float v0 = v.x + sinf(x * div);
    float v1 = v.y + cosf(y * div);
    *(float2*)(lf + (size_t)idx * 2) = make_float2(v0, v1);
    uint32_t hi, lo;
    split_pack_bf2(v0, v1, hi, lo);
    lfhi[idx] = hi;
    lflo[idx] = lo;
}

// ---------------------------------------------------------------------------
// PE global: transpose + PE -> packed bf16 hi/lo
// ---------------------------------------------------------------------------
__global__ __launch_bounds__(256) void pe_global_kernel(const float* __restrict__ in,
                                                        uint32_t* __restrict__ gfhi,
                                                        uint32_t* __restrict__ gflo) {
    __shared__ float tile[32][33];
    const int tid = threadIdx.x;
    const int tx = tid & 31;
    const int ty = tid >> 5;
    const int t0 = blockIdx.x << 5;
    const int d0 = blockIdx.y << 5;
    const int b  = blockIdx.z;

    #pragma unroll
    for (int i = 0; i < 4; i++) {
        int d = d0 + ty + i * 8;
        tile[ty + i * 8][tx] = in[((size_t)b * DD + d) * HWT + t0 + tx];
    }
    __syncthreads();

    const int dp = tid & 15;
    #pragma unroll
    for (int i = 0; i < 2; i++) {
        int tr = (tid >> 4) + i * 16;
        int t = t0 + tr;
        int d = d0 + 2 * dp;
        float div = expf((float)d * (-LN10K / 256.0f));
        float x = (float)(t & 63) * (1.0f / 63.0f);
        float y = (float)(t >> 6) * (1.0f / 63.0f);
        float v0 = tile[2 * dp][tr]     + sinf(x * div);
        float v1 = tile[2 * dp + 1][tr] + cosf(y * div);
        uint32_t hi, lo;
        split_pack_bf2(v0, v1, hi, lo);
        size_t o = ((size_t)b * HWT + t) * 128 + d0 / 2 + dp;
        gfhi[o] = hi;
        gflo[o] = lo;
    }
}

// ---------------------------------------------------------------------------
// Split weights (Wk,Wv stacked); bias bk||bv
// ---------------------------------------------------------------------------
__global__ void split_w_kernel(const float* __restrict__ Wq, const float* __restrict__ Wk,
                               const float* __restrict__ Wv, const float* __restrict__ Wo,
                               const float* __restrict__ bk, const float* __restrict__ bv,
                               uint32_t* __restrict__ wqh, uint32_t* __restrict__ wql,
                               uint32_t* __restrict__ wkvh, uint32_t* __restrict__ wkvl,
                               uint32_t* __restrict__ woh, uint32_t* __restrict__ wol,
                               float* __restrict__ bkv) {
    int idx = blockIdx.x * blockDim.x + threadIdx.x;
    int m = blockIdx.y;
    const float* W; uint32_t *oh, *ol;
    if (m == 0)      { W = Wq; oh = wqh;          ol = wql;          }
    else if (m == 1) { W = Wk; oh = wkvh;         ol = wkvl;         }
    else if (m == 2) { W = Wv; oh = wkvh + 32768; ol = wkvl + 32768; }
    else             { W = Wo; oh = woh;          ol = wol;          }
    float2 v = *(const float2*)(W + (size_t)idx * 2);
    uint32_t hi, lo;
    split_pack_bf2(v.x, v.y, hi, lo);
    oh[idx] = hi;
    ol[idx] = lo;
    if (m == 0 && idx < 512)
        bkv[idx] = (idx < 256) ? bk[idx] : bv[idx - 256];
}

// ---------------------------------------------------------------------------
// bf16x3 GEMM body (128x128 tile), ldmatrix fragment loads.
// ---------------------------------------------------------------------------
struct GemmArgs {
    const uint32_t *Ahi, *Alo, *Whi, *Wlo;
    const float* bias;
    void* Cout;
    int mBase, nBase, ldc;
    float scale;
    int outhalf;
};

__device__ __forceinline__ void gemm_tile_body(const GemmArgs& ga) {
    __shared__ uint32_t sAh[2][128][12];
    __shared__ uint32_t sAl[2][128][12];
    __shared__ uint32_t sWh[2][128][12];
    __shared__ uint32_t sWl[2][128][12];

    const int tid  = threadIdx.x;
    const int warp = tid >> 5;
    const int lane = tid & 31;
    const int gi = lane >> 2;
    const int ci = lane & 3;
    const int wm = (warp & 3) << 5;
    const int wn = (warp >> 2) << 6;

    const int arr = tid >> 6;
    const int r0 = (tid & 63) * 2;
    const uint32_t* gsrc = (arr == 0) ? ga.Ahi + (size_t)ga.mBase * 128
                         : (arr == 1) ? ga.Alo + (size_t)ga.mBase * 128
                         : (arr == 2) ? ga.Whi + (size_t)ga.nBase * 128
                                      : ga.Wlo + (size_t)ga.nBase * 128;
    uint32_t sdst = (arr == 0) ? smem_u32(&sAh[0][0][0])
                  : (arr == 1) ? smem_u32(&sAl[0][0][0])
                  : (arr == 2) ? smem_u32(&sWh[0][0][0])
                               : smem_u32(&sWl[0][0][0]);
    const uint32_t stageBytes = 128 * 12 * 4;

    // ldmatrix per-lane byte offsets (within a stage)
    const int l = lane;
    const uint32_t offA0 = ((uint32_t)((wm +      (l & 15)) * 12 + (l >> 4) * 4)) * 4;
    const uint32_t offA1 = ((uint32_t)((wm + 16 + (l & 15)) * 12 + (l >> 4) * 4)) * 4;
    const uint32_t offB  = ((uint32_t)((wn + (l & 7) + (l >> 4) * 8) * 12
                                       + ((l >> 3) & 1) * 4)) * 4;

    float acc[2][8][4];
    #pragma unroll
    for (int mt = 0; mt < 2; mt++)
        #pragma unroll
        for (int nt = 0; nt < 8; nt++)
            #pragma unroll
            for (int i = 0; i < 4; i++) acc[mt][nt][i] = 0.0f;

    #pragma unroll
    for (int j = 0; j < 4; j++) {
        int row = r0 + (j >> 1), half = j & 1;
        cp16(sdst + (row * 12 + half * 4) * 4, gsrc + (size_t)row * 128 + half * 4);
    }
    asm volatile("cp.async.commit_group;\n");

    const uint32_t bAh = smem_u32(&sAh[0][0][0]);
    const uint32_t bAl = smem_u32(&sAl[0][0][0]);
    const uint32_t bWh = smem_u32(&sWh[0][0][0]);
    const uint32_t bWl = smem_u32(&sWl[0][0][0]);

    for (int kt = 0; kt < 16; kt++) {
        const int buf = kt & 1;
        if (kt < 15) {
            const int k0u = (kt + 1) * 8;
            uint32_t d2 = sdst + (buf ^ 1) * stageBytes;
            #pragma unroll
            for (int j = 0; j < 4; j++) {
                int row = r0 + (j >> 1), half = j & 1;
                cp16(d2 + (row * 12 + half * 4) * 4, gsrc + (size_t)row * 128 + k0u + half * 4);
            }
            asm volatile("cp.async.commit_group;\n");
            asm volatile("cp.async.wait_group 1;\n");
        } else {
            asm volatile("cp.async.wait_group 0;\n");
        }
        __syncthreads();

        const uint32_t so = buf * stageBytes;
        uint32_t ah[2][4], al[2][4];
        ldsm_x4(ah[0][0], ah[0][1], ah[0][2], ah[0][3], bAh + so + offA0);
        ldsm_x4(ah[1][0], ah[1][1], ah[1][2], ah[1][3], bAh + so + offA1);
        ldsm_x4(al[0][0], al[0][1], al[0][2], al[0][3], bAl + so + offA0);
        ldsm_x4(al[1][0], al[1][1], al[1][2], al[1][3], bAl + so + offA1);

        #pragma unroll
        for (int p = 0; p < 4; p++) {
            uint32_t bh[4], bl[4];
            ldsm_x4(bh[0], bh[1], bh[2], bh[3], bWh + so + offB + p * 768);
            ldsm_x4(bl[0], bl[1], bl[2], bl[3], bWl + so + offB + p * 768);
            #pragma unroll
            for (int e = 0; e < 2; e++) {
                int nt = 2 * p + e;
                uint32_t bh0 = bh[2 * e], bh1 = bh[2 * e + 1];
                uint32_t bl0 = bl[2 * e], bl1 = bl[2 * e + 1];
                #pragma unroll
                for (int mt = 0; mt < 2; mt++) {
                    mma_bf16(acc[mt][nt][0], acc[mt][nt][1], acc[mt][nt][2], acc[mt][nt][3],
                             al[mt], bh0, bh1);
                    mma_bf16(acc[mt][nt][0], acc[mt][nt][1], acc[mt][nt][2], acc[mt][nt][3],
                             ah[mt], bl0, bl1);
                    mma_bf16(acc[mt][nt][0], acc[mt][nt][1], acc[mt][nt][2], acc[mt][nt][3],
                             ah[mt], bh0, bh1);
                }
            }
        }
        __syncthreads();
    }

    #pragma unroll
    for (int mt = 0; mt < 2; mt++) {
        #pragma unroll
        for (int nt = 0; nt < 8; nt++) {
            int ncol = ga.nBase + wn + nt * 8 + 2 * ci;
            float2 bs = *(const float2*)(ga.bias + ncol);
            int row = ga.mBase + wm + mt * 16 + gi;
            float c00 = (acc[mt][nt][0] + bs.x) * ga.scale;
            float c01 = (acc[mt][nt][1] + bs.y) * ga.scale;
            float c10 = (acc[mt][nt][2] + bs.x) * ga.scale;
            float c11 = (acc[mt][nt][3] + bs.y) * ga.scale;
            if (ga.outhalf) {
                uint32_t* C = (uint32_t*)ga.Cout;
                C[(size_t)row * (ga.ldc / 2) + ncol / 2]       = pack_h2(c00, c01);
                C[(size_t)(row + 8) * (ga.ldc / 2) + ncol / 2] = pack_h2(c10, c11);
            } else {
                float* C = (float*)ga.Cout;
                *(float2*)(C + (size_t)row * 256 + ncol)       = make_float2(c00, c01);
                *(float2*)(C + (size_t)(row + 8) * 256 + ncol) = make_float2(c10, c11);
            }
        }
    }
}

// Merged Q + KV projection: blocks [0,64) do Q, [64,576) do KV.
// __launch_bounds__(256, 2) caps regs at 128 so 2 blocks fit per SM.
__global__ __launch_bounds__(256, 2) void gemm_qkv_kernel(
    const uint32_t* __restrict__ lfhi, const uint32_t* __restrict__ lflo,
    const uint32_t* __restrict__ gfhi, const uint32_t* __restrict__ gflo,
    const uint32_t* __restrict__ wqh,  const uint32_t* __restrict__ wql,
    const uint32_t* __restrict__ wkvh, const uint32_t* __restrict__ wkvl,
    const float* __restrict__ bq, const float* __restrict__ bkv,
    __half* __restrict__ qout, __half* __restrict__ kvout)
{
    GemmArgs ga;
    ga.outhalf = 1;
    int bid = blockIdx.x;
    if (bid >= 64) {                       // KV: N=512, M=16384
        int kvb = bid - 64;
        int bx = kvb & 3, by = kvb >> 2;
        ga.Ahi = gfhi; ga.Alo = gflo;
        ga.Whi = wkvh; ga.Wlo = wkvl;
        ga.bias = bkv; ga.Cout = kvout;
        ga.mBase = by << 7; ga.nBase = bx << 7; ga.ldc = 512;
        ga.scale = (ga.nBase < 256) ? KSCALE_EX2 : 1.0f;
    } else {                               // Q: N=256, M=4096
        int q = bid;
        int bx = q & 1, by = q >> 1;
        ga.Ahi = lfhi; ga.Alo = lflo;
        ga.Whi = wqh;  ga.Wlo = wql;
        ga.bias = bq;  ga.Cout = qout;
        ga.mBase = by << 7; ga.nBase = bx << 7; ga.ldc = 256;
        ga.scale = 1.0f;
    }
    gemm_tile_body(ga);
}

// ---------------------------------------------------------------------------
// O projection: 64x128 tiles (grid 2 x 64 = 128 blocks), fp32 out.
// ---------------------------------------------------------------------------
__global__ __launch_bounds__(256, 2) void gemm_o_kernel(
    const uint32_t* __restrict__ Ahi, const uint32_t* __restrict__ Alo,
    const uint32_t* __restrict__ Whi, const uint32_t* __restrict__ Wlo,
    const float* __restrict__ bias, float* __restrict__ C)
{
    __shared__ uint32_t sAh[2][64][12];
    __shared__ uint32_t sAl[2][64][12];
    __shared__ uint32_t sWh[2][128][12];
    __shared__ uint32_t sWl[2][128][12];

    const int tid  = threadIdx.x;
    const int warp = tid >> 5;
    const int lane = tid & 31;
    const int gi = lane >> 2;
    const int ci = lane & 3;
    const int mBase = (int)blockIdx.y << 6;
    const int nBase = (int)blockIdx.x << 7;
    const int wm = (warp & 3) << 4;    // 0,16,32,48
    const int wn = (warp >> 2) << 6;   // 0,64

    const int arr = tid >> 6;
    const int t64 = tid & 63;
    const uint32_t aStage = 64 * 12 * 4;
    const uint32_t wStage = 128 * 12 * 4;

    const int l = lane;
    const uint32_t offA = ((uint32_t)((wm + (l & 15)) * 12 + (l >> 4) * 4)) * 4;
    const uint32_t offB = ((uint32_t)((wn + (l & 7) + (l >> 4) * 8) * 12
                                      + ((l >> 3) & 1) * 4)) * 4;
    const uint32_t bAh = smem_u32(&sAh[0][0][0]);
    const uint32_t bAl = smem_u32(&sAl[0][0][0]);
    const uint32_t bWh = smem_u32(&sWh[0][0][0]);
    const uint32_t bWl = smem_u32(&sWl[0][0][0]);

    float acc[8][4];
    #pragma unroll
    for (int nt = 0; nt < 8; nt++)
        #pragma unroll
        for (int i = 0; i < 4; i++) acc[nt][i] = 0.0f;

    #define O_COPY(st, k0u)                                                          \
        do {                                                                         \
            if (arr == 0) {                                                          \
                cp16(bAh + (st) * aStage + (t64 * 12) * 4,                           \
                     Ahi + (size_t)(mBase + t64) * 128 + (k0u));                     \
                cp16(bAh + (st) * aStage + (t64 * 12 + 4) * 4,                       \
                     Ahi + (size_t)(mBase + t64) * 128 + (k0u) + 4);                 \
            } else if (arr == 1) {                                                   \
                cp16(bAl + (st) * aStage + (t64 * 12) * 4,                           \
                     Alo + (size_t)(mBase + t64) * 128 + (k0u));                     \
                cp16(bAl + (st) * aStage + (t64 * 12 + 4) * 4,                       \
                     Alo + (size_t)(mBase + t64) * 128 + (k0u) + 4);                 \
            } else if (arr == 2) {                                                   \
                _Pragma("unroll")                                                    \
                for (int j = 0; j < 4; j++) {                                        \
                    int row = t64 * 2 + (j >> 1), half = j & 1;                      \
                    cp16(bWh + (st) * wStage + (row * 12 + half * 4) * 4,            \
                         Whi + (size_t)(nBase + row) * 128 + (k0u) + half * 4);      \
                }                                                                    \
            } else {                                                                 \
                _Pragma("unroll")                                                    \
                for (int j = 0; j < 4; j++) {                                        \
                    int row = t64 * 2 + (j >> 1), half = j & 1;                      \
                    cp16(bWl + (st) * wStage + (row * 12 + half * 4) * 4,            \
                         Wlo + (size_t)(nBase + row) * 128 + (k0u) + half * 4);      \
                }                                                                    \
            }                                                                        \
        } while (0)

    O_COPY(0, 0);
    asm volatile("cp.async.commit_group;\n");

    for (int kt = 0; kt < 16; kt++) {
        const int buf = kt & 1;
        if (kt < 15) {
            O_COPY(buf ^ 1, (kt + 1) * 8);
            asm volatile("cp.async.commit_group;\n");
            asm volatile("cp.async.wait_group 1;\n");
        } else {
            asm volatile("cp.async.wait_group 0;\n");
        }
        __syncthreads();

        uint32_t ah[4], al[4];
        ldsm_x4(ah[0], ah[1], ah[2], ah[3], bAh + buf * aStage + offA);
        ldsm_x4(al[0], al[1], al[2], al[3], bAl + buf * aStage + offA);

        #pragma unroll
        for (int p = 0; p < 4; p++) {
            uint32_t bh[4], bl[4];
            ldsm_x4(bh[0], bh[1], bh[2], bh[3], bWh + buf * wStage + offB + p * 768);
            ldsm_x4(bl[0], bl[1], bl[2], bl[3], bWl + buf * wStage + offB + p * 768);
            #pragma unroll
            for (int e = 0; e < 2; e++) {
                int nt = 2 * p + e;
                mma_bf16(acc[nt][0], acc[nt][1], acc[nt][2], acc[nt][3],
                         al, bh[2 * e], bh[2 * e + 1]);
                mma_bf16(acc[nt][0], acc[nt][1], acc[nt][2], acc[nt][3],
                         ah, bl[2 * e], bl[2 * e + 1]);
                mma_bf16(acc[nt][0], acc[nt][1], acc[nt][2], acc[nt][3],
                         ah, bh[2 * e], bh[2 * e + 1]);
            }
        }
        __syncthreads();
    }
    #undef O_COPY

    #pragma unroll
    for (int nt = 0; nt < 8; nt++) {
        int ncol = nBase + wn + nt * 8 + 2 * ci;
        float2 bs = *(const float2*)(bias + ncol);
        int row = mBase + wm + gi;
        *(float2*)(C + (size_t)row * 256 + ncol) =
            make_float2(acc[nt][0] + bs.x, acc[nt][1] + bs.y);
        *(float2*)(C + (size_t)(row + 8) * 256 + ncol) =
            make_float2(acc[nt][2] + bs.x, acc[nt][3] + bs.y);
    }
}

// ---------------------------------------------------------------------------
// Flash attention: 256 queries/block (8 warps x 32), KV tile 64, double buffer.
// Scores in exp2 domain; P via ex2.approx.f16x2; row-sum l via ones-MMA.
// ---------------------------------------------------------------------------
__global__ __launch_bounds__(256, 2) void flash_mma_kernel(
    const __half* __restrict__ q, const __half* __restrict__ kv,
    const float* __restrict__ lf,
    uint32_t* __restrict__ tmphi, uint32_t* __restrict__ tmplo)
{
    __shared__ uint32_t Kh[2][64][20];
    __shared__ __half   Vsh[2][64][40];

    const int tid  = threadIdx.x;
    const int warp = tid >> 5;
    const int lane = tid & 31;
    const int gi = lane >> 2;
    const int ci = lane & 3;
    const int b = blockIdx.z;
    const int h = blockIdx.y;
    const int qbase = (blockIdx.x << 8) + warp * 32;

    uint32_t qh[2][2][4];
    {
        const __half* qp = q + ((size_t)(b * NP + qbase)) * DD + h * DH;
        #pragma unroll
        for (int mt = 0; mt < 2; mt++)
            #pragma unroll
            for (int s = 0; s < 2; s++)
                #pragma unroll
                for (int r = 0; r < 4; r++) {
                    int row = mt * 16 + gi + (r & 1) * 8;
                    int col = s * 16 + 2 * ci + (r >> 1) * 8;
                    qh[mt][s][r] = *(const uint32_t*)(qp + (size_t)row * DD + col);
                }
    }

    float O[2][4][4];
    #pragma unroll
    for (int mt = 0; mt < 2; mt++)
        #pragma unroll
        for (int n = 0; n < 4; n++)
            #pragma unroll
            for (int i = 0; i < 4; i++) O[mt][n][i] = 0.0f;
    float Lc[2][4];
    float mM[2][2];
    #pragma unroll
    for (int mt = 0; mt < 2; mt++) {
        Lc[mt][0] = Lc[mt][1] = Lc[mt][2] = Lc[mt][3] = 0.0f;
        mM[mt][0] = -1e30f; mM[mt][1] = -1e30f;
    }

    const __half* kbase = kv + (size_t)b * HWT * 512 + h * DH;
    const __half* vbase = kv + (size_t)b * HWT * 512 + 256 + h * DH;

    const uint32_t offK = ((uint32_t)((lane & 7) * 20 + (lane >> 3) * 4)) * 4;
    const uint32_t kStage = 64 * 20 * 4;
    const uint32_t bK = smem_u32(&Kh[0][0][0]);

    {
        int key = tid >> 2, ch = tid & 3;
        cp16(smem_u32(&Kh[0][key][ch * 4]),  kbase + (size_t)key * 512 + ch * 8);
        cp16(smem_u32(&Vsh[0][key][ch * 8]), vbase + (size_t)key * 512 + ch * 8);
    }
    asm volatile("cp.async.commit_group;\n");

    for (int t = 0; t < 64; t++) {
        const int buf = t & 1;
        asm volatile("cp.async.wait_group 0;\n");
        __syncthreads();
        if (t < 63) {
            const size_t kv0 = (size_t)(t + 1) << 6;
            int key = tid >> 2, ch = tid & 3;
            cp16(smem_u32(&Kh[buf ^ 1][key][ch * 4]),
                 kbase + (kv0 + key) * 512 + ch * 8);
            cp16(smem_u32(&Vsh[buf ^ 1][key][ch * 8]),
                 vbase + (kv0 + key) * 512 + ch * 8);
            asm volatile("cp.async.commit_group;\n");
        }

        #pragma unroll
        for (int mt = 0; mt < 2; mt++) {
            float Sf[8][4];
            #pragma unroll
            for (int nt = 0; nt < 8; nt++) {
                uint32_t B0, B1, B2, B3;
                ldsm_x4(B0, B1, B2, B3, bK + buf * kStage + offK + nt * 640);
                float c0 = 0.f, c1 = 0.f, c2 = 0.f, c3 = 0.f;
                mma_f16(c0, c1, c2, c3,
                        qh[mt][0][0], qh[mt][0][1], qh[mt][0][2], qh[mt][0][3], B0, B1);
                mma_f16(c0, c1, c2, c3,
                        qh[mt][1][0], qh[mt][1][1], qh[mt][1][2], qh[mt][1][3], B2, B3);
                Sf[nt][0] = c0; Sf[nt][1] = c1; Sf[nt][2] = c2; Sf[nt][3] = c3;
            }

            float mx0 = -1e30f, mx1 = -1e30f;
            #pragma unroll
            for (int nt = 0; nt < 8; nt++) {
                mx0 = fmaxf(mx0, fmaxf(Sf[nt][0], Sf[nt][1]));
                mx1 = fmaxf(mx1, fmaxf(Sf[nt][2], Sf[nt][3]));
            }
            mx0 = fmaxf(mx0, __shfl_xor_sync(0xffffffffu, mx0, 1));
            mx0 = fmaxf(mx0, __shfl_xor_sync(0xffffffffu, mx0, 2));
            mx1 = fmaxf(mx1, __shfl_xor_sync(0xffffffffu, mx1, 1));
            mx1 = fmaxf(mx1, __shfl_xor_sync(0xffffffffu, mx1, 2));

            float mn0 = fmaxf(mM[mt][0], mx0), mn1 = fmaxf(mM[mt][1], mx1);
            float corr0 = ex2(mM[mt][0] - mn0), corr1 = ex2(mM[mt][1] - mn1);
            mM[mt][0] = mn0; mM[mt][1] = mn1;

            #pragma unroll
            for (int n = 0; n < 4; n++) {
                O[mt][n][0] *= corr0; O[mt][n][1] *= corr0;
                O[mt][n][2] *= corr1; O[mt][n][3] *= corr1;
            }
            Lc[mt][0] *= corr0; Lc[mt][1] *= corr0;
            Lc[mt][2] *= corr1; Lc[mt][3] *= corr1;

            #pragma unroll
            for (int s = 0; s < 4; s++) {
                uint32_t a0 = h2ex2(pack_h2(Sf[2 * s][0] - mn0,     Sf[2 * s][1] - mn0));
                uint32_t a1 = h2ex2(pack_h2(Sf[2 * s][2] - mn1,     Sf[2 * s][3] - mn1));
                uint32_t a2 = h2ex2(pack_h2(Sf[2 * s + 1][0] - mn0, Sf[2 * s + 1][1] - mn0));
                uint32_t a3 = h2ex2(pack_h2(Sf[2 * s + 1][2] - mn1, Sf[2 * s + 1][3] - mn1));

                mma_f16(Lc[mt][0], Lc[mt][1], Lc[mt][2], Lc[mt][3],
                        a0, a1, a2, a3, ONES_H2, ONES_H2);

                int mi = lane >> 3;
                int key = s * 16 + (mi & 1) * 8 + (lane & 7);
                #pragma unroll
                for (int db = 0; db < 2; db++) {
                    int dh0 = db * 16 + (mi >> 1) * 8;
                    uint32_t B0, B1, B2, B3;
                    ldsm_x4_trans(B0, B1, B2, B3, smem_u32(&Vsh[buf][key][dh0]));
                    mma_f16(O[mt][2 * db][0],     O[mt][2 * db][1],
                            O[mt][2 * db][2],     O[mt][2 * db][3],
                            a0, a1, a2, a3, B0, B1);
                    mma_f16(O[mt][2 * db + 1][0], O[mt][2 * db + 1][1],
                            O[mt][2 * db + 1][2], O[mt][2 * db + 1][3],
                            a0, a1, a2, a3, B2, B3);
                }
            }
        }
    }

    // Epilogue: out = O/l + lf, packed bf16 hi/lo for O-projection
    const float* lfp = lf + ((size_t)(b * NP + qbase)) * DD + h * DH;
    uint32_t* th = tmphi + ((size_t)(b * NP + qbase)) * 128 + h * (DH / 2);
    uint32_t* tl = tmplo + ((size_t)(b * NP + qbase)) * 128 + h * (DH / 2);
    #pragma unroll
    for (int mt = 0; mt < 2; mt++) {
        float inv0 = 1.0f / Lc[mt][0], inv1 = 1.0f / Lc[mt][2];
        #pragma unroll
        for (int n = 0; n < 4; n++) {
            int row0 = mt * 16 + gi, row1 = row0 + 8;
            int col = n * 8 + 2 * ci;
            float2 L0 = *(const float2*)(lfp + (size_t)row0 * DD + col);
            float2 L1 = *(const float2*)(lfp + (size_t)row1 * DD + col);
            float a0 = O[mt][n][0] * inv0 + L0.x;
            float a1 = O[mt][n][1] * inv0 + L0.y;
            float b0 = O[mt][n][2] * inv1 + L1.x;
            float b1 = O[mt][n][3] * inv1 + L1.y;
            uint32_t hi, lo;
            split_pack_bf2(a0, a1, hi, lo);
            th[(size_t)row0 * 128 + col / 2] = hi;
            tl[(size_t)row0 * 128 + col / 2] = lo;
            split_pack_bf2(b0, b1, hi, lo);
            th[(size_t)row1 * 128 + col / 2] = hi;
            tl[(size_t)row1 * 128 + col / 2] = lo;
        }
    }
}

// ---------------------------------------------------------------------------
extern "C" void kernel_launch(void* const* d_in, const int* in_sizes, int n_in,
                              void* d_out, int out_size) {
    const float* local_feat  = (const float*)d_in[0];
    const float* global_feat = (const float*)d_in[1];
    const float* Wq = (const float*)d_in[2];
    const float* bq = (const float*)d_in[3];
    const float* Wk = (const float*)d_in[4];
    const float* bk = (const float*)d_in[5];
    const float* Wv = (const float*)d_in[6];
    const float* bv = (const float*)d_in[7];
    const float* Wo = (const float*)d_in[8];
    const float* bo = (const float*)d_in[9];
    float* out = (float*)d_out;

    float* base = nullptr;
    cudaGetSymbolAddress((void**)&base, g_scratch);
    float* lf = base;
    __half* q  = (__half*)(lf + LF_ELEMS);
    __half* kv = q + LF_ELEMS;
    uint32_t* lfhi  = (uint32_t*)(kv + 8 * 1024 * 1024);
    uint32_t* lflo  = lfhi  + LF_ELEMS / 2;
    uint32_t* gfhi  = lflo  + LF_ELEMS / 2;
    uint32_t* gflo  = gfhi  + GF_ELEMS / 2;
    uint32_t* tmphi = gflo  + GF_ELEMS / 2;
    uint32_t* tmplo = tmphi + LF_ELEMS / 2;
    uint32_t* wqh   = tmplo + LF_ELEMS / 2;
    uint32_t* wql   = wqh + 32768;
    uint32_t* wkvh  = wql + 32768;
    uint32_t* wkvl  = wkvh + 65536;
    uint32_t* woh   = wkvl + 65536;
    uint32_t* wol   = woh + 32768;
    float*    bkv   = (float*)(wol + 32768);

    split_w_kernel<<<dim3(128, 4), 256>>>(Wq, Wk, Wv, Wo, bk, bv,
                                          wqh, wql, wkvh, wkvl, woh, wol, bkv);
    pe_local_kernel<<<(int)(LF_ELEMS / 2 / 256), 256>>>(local_feat, lf, lfhi, lflo);
    pe_global_kernel<<<dim3(HWT / 32, DD / 32, NB), 256>>>(global_feat, gfhi, gflo);

    gemm_qkv_kernel<<<576, 256>>>(lfhi, lflo, gfhi, gflo,
                                  wqh, wql, wkvh, wkvl, bq, bkv, q, kv);

    flash_mma_kernel<<<dim3(NP / 256, HEADS, NB), 256>>>(q, kv, lf, tmphi, tmplo);

    gemm_o_kernel<<<dim3(2, 64), 256>>>(tmphi, tmplo, woh, wol, bo, out);
}